// round 1
// baseline (speedup 1.0000x reference)
#include <cuda_runtime.h>
#include <math.h>

#define D_MODEL 1024
#define HEADS   16
#define DH      64
#define BATCH   4
#define SEQ     2048
#define M_TOTAL (BATCH * SEQ)   // 8192

// ---------------- scratch (device globals: allocation-guard safe) ----------------
__device__ float g_qh[(size_t)BATCH * HEADS * SEQ * DH];   // [B,H,L,Dh]
__device__ float g_kh[(size_t)BATCH * HEADS * SEQ * DH];
__device__ float g_vh[(size_t)BATCH * HEADS * SEQ * DH];
__device__ float g_att[(size_t)M_TOTAL * D_MODEL];         // [B*L, D_MODEL]

// ---------------- SGEMM: C[M,1024] = A[M,1024] @ W[1024,1024] + bias ----------------
// BM=BN=128, BK=8, 256 threads, 8x8 per thread.
// HEADSPLIT=1 writes C in [B,H,L,Dh] layout for the attention kernel.
template <int HEADSPLIT>
__global__ __launch_bounds__(256) void sgemm_bias(
    const float* __restrict__ A, const float* __restrict__ W,
    const float* __restrict__ bias, float* __restrict__ C)
{
    const int K = D_MODEL, N = D_MODEL;
    const int BM = 128, BN = 128, BK = 8;

    __shared__ float As[BK][BM];   // transposed A tile
    __shared__ float Bs[BK][BN];

    const int tid = threadIdx.x;
    const int tx = tid & 15;       // 0..15 -> 8 cols each
    const int ty = tid >> 4;       // 0..15 -> 8 rows each
    const int bm = blockIdx.y * BM;
    const int bn = blockIdx.x * BN;

    float acc[8][8];
#pragma unroll
    for (int i = 0; i < 8; i++)
#pragma unroll
        for (int j = 0; j < 8; j++) acc[i][j] = 0.f;

    const int aRow = tid >> 1;           // 0..127
    const int aCol = (tid & 1) * 4;      // 0 or 4
    const int wRow = tid >> 5;           // 0..7
    const int wCol = (tid & 31) * 4;     // 0..124

    const float* Aptr = A + (size_t)(bm + aRow) * K + aCol;
    const float* Wptr = W + (size_t)wRow * N + bn + wCol;

    for (int k0 = 0; k0 < K; k0 += BK) {
        float4 av = *(const float4*)(Aptr + k0);
        As[aCol + 0][aRow] = av.x;
        As[aCol + 1][aRow] = av.y;
        As[aCol + 2][aRow] = av.z;
        As[aCol + 3][aRow] = av.w;
        *(float4*)&Bs[wRow][wCol] = *(const float4*)(Wptr + (size_t)k0 * N);
        __syncthreads();

#pragma unroll
        for (int kk = 0; kk < BK; kk++) {
            float a[8], b[8];
            *(float4*)(a)     = *(float4*)&As[kk][ty * 8];
            *(float4*)(a + 4) = *(float4*)&As[kk][ty * 8 + 4];
            *(float4*)(b)     = *(float4*)&Bs[kk][tx * 8];
            *(float4*)(b + 4) = *(float4*)&Bs[kk][tx * 8 + 4];
#pragma unroll
            for (int i = 0; i < 8; i++)
#pragma unroll
                for (int j = 0; j < 8; j++)
                    acc[i][j] = fmaf(a[i], b[j], acc[i][j]);
        }
        __syncthreads();
    }

#pragma unroll
    for (int i = 0; i < 8; i++) {
        const int row = bm + ty * 8 + i;
#pragma unroll
        for (int j = 0; j < 8; j++) {
            const int col = bn + tx * 8 + j;
            const float v = acc[i][j] + bias[col];
            if (HEADSPLIT) {
                const int b = row >> 11;           // row / SEQ
                const int l = row & (SEQ - 1);
                const int h = col >> 6;            // col / DH
                const int d = col & 63;
                C[(((size_t)(b * HEADS + h) * SEQ + l) << 6) + d] = v;
            } else {
                C[(size_t)row * N + col] = v;
            }
        }
    }
}

// ---------------- causal flash attention (fp32), per (b,h) in [L,Dh] layout ----------------
// grid: (L/64, B*H), 256 threads; 64x64 tiles; thread computes 4x4 fragments.
#define BQ 64
#define BKT 64
#define PAD 68   // stride 68 floats: 16B-aligned rows, rotates banks by 4/row

__global__ __launch_bounds__(256) void flash_attn_kernel(
    const float* __restrict__ Q, const float* __restrict__ K,
    const float* __restrict__ V, float* __restrict__ O)
{
    extern __shared__ float sm[];
    float* Qs = sm;                  // 64*68
    float* Ks = Qs + BQ * PAD;
    float* Vs = Ks + BKT * PAD;
    float* Ps = Vs + BKT * PAD;

    const int tid = threadIdx.x;
    const int tx = tid & 15;         // key/dh column group (4 each)
    const int ty = tid >> 4;         // query row group (4 each)
    const int bh = blockIdx.y;
    const int qt = blockIdx.x;
    const int q0 = qt * BQ;

    const float* Qb = Q + (size_t)bh * SEQ * DH;
    const float* Kb = K + (size_t)bh * SEQ * DH;
    const float* Vb = V + (size_t)bh * SEQ * DH;

    // load Q tile (64x64): 1024 float4s across 256 threads
#pragma unroll
    for (int t = 0; t < 4; t++) {
        const int i = tid + t * 256;
        const int r = i >> 4, c4 = (i & 15) * 4;
        *(float4*)&Qs[r * PAD + c4] = *(const float4*)&Qb[(size_t)(q0 + r) * DH + c4];
    }

    float m[4], l[4], o[4][4];
#pragma unroll
    for (int i = 0; i < 4; i++) {
        m[i] = -INFINITY; l[i] = 0.f;
#pragma unroll
        for (int j = 0; j < 4; j++) o[i][j] = 0.f;
    }

    const float scale = 0.125f;   // 1/sqrt(64)

    for (int kt = 0; kt <= qt; kt++) {
        const int k0 = kt * BKT;
#pragma unroll
        for (int t = 0; t < 4; t++) {
            const int i = tid + t * 256;
            const int r = i >> 4, c4 = (i & 15) * 4;
            *(float4*)&Ks[r * PAD + c4] = *(const float4*)&Kb[(size_t)(k0 + r) * DH + c4];
            *(float4*)&Vs[r * PAD + c4] = *(const float4*)&Vb[(size_t)(k0 + r) * DH + c4];
        }
        __syncthreads();

        // S = Q K^T fragment (4x4)
        float s[4][4];
#pragma unroll
        for (int i = 0; i < 4; i++)
#pragma unroll
            for (int j = 0; j < 4; j++) s[i][j] = 0.f;

#pragma unroll
        for (int d = 0; d < DH; d++) {
            float a[4], b[4];
#pragma unroll
            for (int i = 0; i < 4; i++) a[i] = Qs[(ty * 4 + i) * PAD + d];
#pragma unroll
            for (int j = 0; j < 4; j++) b[j] = Ks[(tx * 4 + j) * PAD + d];
#pragma unroll
            for (int i = 0; i < 4; i++)
#pragma unroll
                for (int j = 0; j < 4; j++)
                    s[i][j] = fmaf(a[i], b[j], s[i][j]);
        }

        // scale + causal mask (only diagonal tile needs it)
#pragma unroll
        for (int i = 0; i < 4; i++)
#pragma unroll
            for (int j = 0; j < 4; j++) {
                s[i][j] *= scale;
                if (kt == qt && (k0 + tx * 4 + j) > (q0 + ty * 4 + i))
                    s[i][j] = -INFINITY;
            }

        // row max over the 16 threads sharing these 4 rows (lanes form a 16-half)
        float mt[4];
#pragma unroll
        for (int i = 0; i < 4; i++)
            mt[i] = fmaxf(fmaxf(s[i][0], s[i][1]), fmaxf(s[i][2], s[i][3]));
#pragma unroll
        for (int off = 8; off >= 1; off >>= 1)
#pragma unroll
            for (int i = 0; i < 4; i++)
                mt[i] = fmaxf(mt[i], __shfl_xor_sync(0xffffffffu, mt[i], off));

        float corr[4];
#pragma unroll
        for (int i = 0; i < 4; i++) {
            const float mn = fmaxf(m[i], mt[i]);
            corr[i] = __expf(m[i] - mn);
            m[i] = mn;
        }

        // P = exp(S - m), row sums
        float rs[4] = {0.f, 0.f, 0.f, 0.f};
#pragma unroll
        for (int i = 0; i < 4; i++)
#pragma unroll
            for (int j = 0; j < 4; j++) {
                const float p = __expf(s[i][j] - m[i]);
                Ps[(ty * 4 + i) * PAD + tx * 4 + j] = p;
                rs[i] += p;
            }
#pragma unroll
        for (int off = 8; off >= 1; off >>= 1)
#pragma unroll
            for (int i = 0; i < 4; i++)
                rs[i] += __shfl_xor_sync(0xffffffffu, rs[i], off);

#pragma unroll
        for (int i = 0; i < 4; i++) {
            l[i] = l[i] * corr[i] + rs[i];
#pragma unroll
            for (int j = 0; j < 4; j++) o[i][j] *= corr[i];
        }
        __syncthreads();   // Ps visible to all

        // O += P @ V  (tx now indexes Dh columns)
#pragma unroll
        for (int k = 0; k < BKT; k++) {
            float a[4];
#pragma unroll
            for (int i = 0; i < 4; i++) a[i] = Ps[(ty * 4 + i) * PAD + k];
            const float4 b4 = *(float4*)&Vs[k * PAD + tx * 4];
            const float b[4] = {b4.x, b4.y, b4.z, b4.w};
#pragma unroll
            for (int i = 0; i < 4; i++)
#pragma unroll
                for (int j = 0; j < 4; j++)
                    o[i][j] = fmaf(a[i], b[j], o[i][j]);
        }
        __syncthreads();   // done with Ks/Vs/Ps before next tile overwrites
    }

    // write back into [B, L, D_MODEL]
    const int b = bh >> 4, h = bh & 15;
#pragma unroll
    for (int i = 0; i < 4; i++) {
        const int qrow = q0 + ty * 4 + i;
        const float inv = 1.f / l[i];
#pragma unroll
        for (int j = 0; j < 4; j++)
            O[(size_t)(b * SEQ + qrow) * D_MODEL + h * DH + tx * 4 + j] = o[i][j] * inv;
    }
}

// ---------------- launch ----------------
extern "C" void kernel_launch(void* const* d_in, const int* in_sizes, int n_in,
                              void* d_out, int out_size)
{
    const float* q  = (const float*)d_in[0];
    const float* k  = (const float*)d_in[1];
    const float* v  = (const float*)d_in[2];
    const float* Wq = (const float*)d_in[3];
    const float* bq = (const float*)d_in[4];
    const float* Wk = (const float*)d_in[5];
    const float* bk = (const float*)d_in[6];
    const float* Wv = (const float*)d_in[7];
    const float* bv = (const float*)d_in[8];
    const float* Wo = (const float*)d_in[9];
    const float* bo = (const float*)d_in[10];
    float* out = (float*)d_out;

    float *qh, *kh, *vh, *att;
    cudaGetSymbolAddress((void**)&qh,  g_qh);
    cudaGetSymbolAddress((void**)&kh,  g_kh);
    cudaGetSymbolAddress((void**)&vh,  g_vh);
    cudaGetSymbolAddress((void**)&att, g_att);

    const dim3 gemm_grid(D_MODEL / 128, M_TOTAL / 128);   // (8, 64)
    sgemm_bias<1><<<gemm_grid, 256>>>(q, Wq, bq, qh);
    sgemm_bias<1><<<gemm_grid, 256>>>(k, Wk, bk, kh);
    sgemm_bias<1><<<gemm_grid, 256>>>(v, Wv, bv, vh);

    const int smem = 4 * BQ * PAD * sizeof(float);        // ~69.6 KB
    cudaFuncSetAttribute(flash_attn_kernel,
                         cudaFuncAttributeMaxDynamicSharedMemorySize, smem);
    flash_attn_kernel<<<dim3(SEQ / BQ, BATCH * HEADS), 256, smem>>>(qh, kh, vh, att);

    sgemm_bias<0><<<gemm_grid, 256>>>(att, Wo, bo, out);
}

// round 3
// speedup vs baseline: 3.2113x; 3.2113x over previous
#include <cuda_runtime.h>
#include <math.h>
#include <stdint.h>

#define D_MODEL 1024
#define HEADS   16
#define DH      64
#define BATCH   4
#define SEQ     2048
#define M_TOTAL (BATCH * SEQ)   // 8192

// ---------------- scratch (device globals: allocation-guard safe) ----------------
__device__ float g_qh[(size_t)BATCH * HEADS * SEQ * DH];   // [B,H,L,Dh]
__device__ float g_kh[(size_t)BATCH * HEADS * SEQ * DH];
__device__ float g_vh[(size_t)BATCH * HEADS * SEQ * DH];
__device__ float g_att[(size_t)M_TOTAL * D_MODEL];         // [B*L, D_MODEL]

// ---------------- tf32 helpers ----------------
__device__ __forceinline__ uint32_t f2tf32(float x) {
    uint32_t r;
    asm("cvt.rna.tf32.f32 %0, %1;" : "=r"(r) : "f"(x));
    return r;
}

__device__ __forceinline__ void mma_tf32(float c[4], const uint32_t a[4], const uint32_t b[2]) {
    asm("mma.sync.aligned.m16n8k8.row.col.f32.tf32.tf32.f32 "
        "{%0,%1,%2,%3}, {%4,%5,%6,%7}, {%8,%9}, {%0,%1,%2,%3};"
        : "+f"(c[0]), "+f"(c[1]), "+f"(c[2]), "+f"(c[3])
        : "r"(a[0]), "r"(a[1]), "r"(a[2]), "r"(a[3]), "r"(b[0]), "r"(b[1]));
}

// ---------------- TF32 GEMM: C[M,1024] = A[M,1024] @ W[1024,1024] + bias ----------------
// BM=BN=128, BK=32, 256 threads (8 warps), warp tile 64x32 (4x4 m16n8k8 frags).
// Smem strides: A=36 (banks 4g+t, conflict-free), B=136 (banks 8t+g, conflict-free).
#define AS_STR 36
#define BS_STR 136

template <int HEADSPLIT>
__global__ __launch_bounds__(256) void gemm_tf32(
    const float* __restrict__ A, const float* __restrict__ W,
    const float* __restrict__ bias, float* __restrict__ C)
{
    __shared__ uint32_t As[128 * AS_STR];
    __shared__ uint32_t Bs[32 * BS_STR];

    const int tid = threadIdx.x;
    const int lane = tid & 31;
    const int w = tid >> 5;
    const int g = lane >> 2;      // groupID (row within mma tile)
    const int t = lane & 3;       // threadID_in_group
    const int wm = w >> 2;        // 0..1 -> 64-row band
    const int wn = w & 3;         // 0..3 -> 32-col band
    const int bm = blockIdx.y * 128;
    const int bn = blockIdx.x * 128;

    float acc[4][4][4];           // [mt][nt][frag]
#pragma unroll
    for (int mt = 0; mt < 4; mt++)
#pragma unroll
        for (int nt = 0; nt < 4; nt++)
#pragma unroll
            for (int i = 0; i < 4; i++) acc[mt][nt][i] = 0.f;

    const int arow = tid >> 1, acol = (tid & 1) * 16;          // A: 128x32 tile
    const int brow = tid >> 3, bcol = (tid & 7) * 16;          // B: 32x128 tile
    const float* Ap = A + (size_t)(bm + arow) * D_MODEL + acol;
    const float* Wp = W + (size_t)brow * D_MODEL + bn + bcol;

    for (int k0 = 0; k0 < D_MODEL; k0 += 32) {
#pragma unroll
        for (int j = 0; j < 4; j++) {
            float4 va = *(const float4*)(Ap + k0 + j * 4);
            uint32_t* d = &As[arow * AS_STR + acol + j * 4];
            d[0] = f2tf32(va.x); d[1] = f2tf32(va.y);
            d[2] = f2tf32(va.z); d[3] = f2tf32(va.w);
        }
#pragma unroll
        for (int j = 0; j < 4; j++) {
            float4 vb = *(const float4*)(Wp + (size_t)k0 * D_MODEL + j * 4);
            uint32_t* d = &Bs[brow * BS_STR + bcol + j * 4];
            d[0] = f2tf32(vb.x); d[1] = f2tf32(vb.y);
            d[2] = f2tf32(vb.z); d[3] = f2tf32(vb.w);
        }
        __syncthreads();

#pragma unroll
        for (int ks = 0; ks < 4; ks++) {
            const int kk = ks * 8;
            uint32_t a[4][4], b[4][2];
#pragma unroll
            for (int mt = 0; mt < 4; mt++) {
                const int r = wm * 64 + mt * 16;
                a[mt][0] = As[(r + g)     * AS_STR + kk + t];
                a[mt][1] = As[(r + g + 8) * AS_STR + kk + t];
                a[mt][2] = As[(r + g)     * AS_STR + kk + t + 4];
                a[mt][3] = As[(r + g + 8) * AS_STR + kk + t + 4];
            }
#pragma unroll
            for (int nt = 0; nt < 4; nt++) {
                const int c = wn * 32 + nt * 8 + g;
                b[nt][0] = Bs[(kk + t)     * BS_STR + c];
                b[nt][1] = Bs[(kk + t + 4) * BS_STR + c];
            }
#pragma unroll
            for (int mt = 0; mt < 4; mt++)
#pragma unroll
                for (int nt = 0; nt < 4; nt++)
                    mma_tf32(acc[mt][nt], a[mt], b[nt]);
        }
        __syncthreads();
    }

    // epilogue
#pragma unroll
    for (int mt = 0; mt < 4; mt++) {
#pragma unroll
        for (int nt = 0; nt < 4; nt++) {
            const int r0 = bm + wm * 64 + mt * 16 + g;
            const int c0 = bn + wn * 32 + nt * 8 + 2 * t;
#pragma unroll
            for (int i = 0; i < 4; i++) {
                const int row = r0 + (i >> 1) * 8;
                const int col = c0 + (i & 1);
                const float v = acc[mt][nt][i] + bias[col];
                if (HEADSPLIT) {
                    const int b = row >> 11, l = row & (SEQ - 1);
                    const int h = col >> 6,  d = col & 63;
                    C[(((size_t)(b * HEADS + h) * SEQ + l) << 6) + d] = v;
                } else {
                    C[(size_t)row * D_MODEL + col] = v;
                }
            }
        }
    }
}

// ---------------- TF32 flash attention (causal), per (b,h), [L,Dh] layout ----------------
// BQ=128, BK=64. 8 warps, warp owns 16 q-rows. Q frags in registers.
// Smem strides: Ks=68 (4g+t), Vs=72 (8t+g), Ps=68 (4g+t) — conflict-free frag loads.
#define KS_STR 68
#define VS_STR 72
#define PS_STR 68

__global__ __launch_bounds__(256) void flash_tf32(
    const float* __restrict__ Q, const float* __restrict__ K,
    const float* __restrict__ V, float* __restrict__ O)
{
    extern __shared__ uint32_t sm[];
    uint32_t* Ks = sm;                       // 64 * 68
    uint32_t* Vs = Ks + 64 * KS_STR;         // 64 * 72
    uint32_t* Ps = Vs + 64 * VS_STR;         // 128 * 68

    const int tid = threadIdx.x;
    const int lane = tid & 31;
    const int w = tid >> 5;                  // warp: q-rows [16w, 16w+16)
    const int g = lane >> 2;
    const int t = lane & 3;
    const int bh = blockIdx.y;
    const int bx = blockIdx.x;
    const int q0 = bx * 128;

    const float* Qb = Q + (size_t)bh * SEQ * DH;
    const float* Kb = K + (size_t)bh * SEQ * DH;
    const float* Vb = V + (size_t)bh * SEQ * DH;

    // Q fragments -> registers (once)
    const int qr = q0 + w * 16 + g;
    uint32_t qa[8][4];
#pragma unroll
    for (int kt = 0; kt < 8; kt++) {
        qa[kt][0] = f2tf32(Qb[(size_t)qr       * DH + kt * 8 + t]);
        qa[kt][1] = f2tf32(Qb[(size_t)(qr + 8) * DH + kt * 8 + t]);
        qa[kt][2] = f2tf32(Qb[(size_t)qr       * DH + kt * 8 + t + 4]);
        qa[kt][3] = f2tf32(Qb[(size_t)(qr + 8) * DH + kt * 8 + t + 4]);
    }

    float oacc[8][4];
#pragma unroll
    for (int dt = 0; dt < 8; dt++)
#pragma unroll
        for (int i = 0; i < 4; i++) oacc[dt][i] = 0.f;
    float m0 = -INFINITY, m1 = -INFINITY, l0 = 0.f, l1 = 0.f;

    const int krow = tid >> 2, kcol = (tid & 3) * 16;
    const int jmax = 2 * bx + 1;

    for (int j = 0; j <= jmax; j++) {
        const int k0 = j * 64;
        __syncthreads();   // previous tile's PV done with Ks/Vs
        const float* kp = Kb + (size_t)(k0 + krow) * DH + kcol;
        const float* vp = Vb + (size_t)(k0 + krow) * DH + kcol;
#pragma unroll
        for (int jj = 0; jj < 4; jj++) {
            float4 kv = *(const float4*)(kp + jj * 4);
            uint32_t* dk = &Ks[krow * KS_STR + kcol + jj * 4];
            dk[0] = f2tf32(kv.x); dk[1] = f2tf32(kv.y);
            dk[2] = f2tf32(kv.z); dk[3] = f2tf32(kv.w);
            float4 vv = *(const float4*)(vp + jj * 4);
            uint32_t* dv = &Vs[krow * VS_STR + kcol + jj * 4];
            dv[0] = f2tf32(vv.x); dv[1] = f2tf32(vv.y);
            dv[2] = f2tf32(vv.z); dv[3] = f2tf32(vv.w);
        }
        __syncthreads();

        // S = Q K^T  (warp's 16 rows x 64 keys)
        float sacc[8][4];
#pragma unroll
        for (int nt = 0; nt < 8; nt++)
#pragma unroll
            for (int i = 0; i < 4; i++) sacc[nt][i] = 0.f;
#pragma unroll
        for (int kt = 0; kt < 8; kt++) {
#pragma unroll
            for (int nt = 0; nt < 8; nt++) {
                uint32_t b[2];
                b[0] = Ks[(nt * 8 + g) * KS_STR + kt * 8 + t];
                b[1] = Ks[(nt * 8 + g) * KS_STR + kt * 8 + t + 4];
                mma_tf32(sacc[nt], qa[kt], b);
            }
        }

        // scale + causal mask
        const bool need_mask = (j >= 2 * bx);
#pragma unroll
        for (int nt = 0; nt < 8; nt++) {
            const int c0 = k0 + nt * 8 + 2 * t;
#pragma unroll
            for (int i = 0; i < 4; i++) {
                sacc[nt][i] *= 0.125f;
                if (need_mask) {
                    const int row = (i >> 1) ? qr + 8 : qr;
                    const int col = c0 + (i & 1);
                    if (col > row) sacc[nt][i] = -INFINITY;
                }
            }
        }

        // row maxes (rows qr and qr+8), reduce over 4 tig lanes
        float mt0 = -INFINITY, mt1 = -INFINITY;
#pragma unroll
        for (int nt = 0; nt < 8; nt++) {
            mt0 = fmaxf(mt0, fmaxf(sacc[nt][0], sacc[nt][1]));
            mt1 = fmaxf(mt1, fmaxf(sacc[nt][2], sacc[nt][3]));
        }
        mt0 = fmaxf(mt0, __shfl_xor_sync(0xffffffffu, mt0, 1));
        mt0 = fmaxf(mt0, __shfl_xor_sync(0xffffffffu, mt0, 2));
        mt1 = fmaxf(mt1, __shfl_xor_sync(0xffffffffu, mt1, 1));
        mt1 = fmaxf(mt1, __shfl_xor_sync(0xffffffffu, mt1, 2));

        const float mn0 = fmaxf(m0, mt0), mn1 = fmaxf(m1, mt1);
        const float cor0 = __expf(m0 - mn0), cor1 = __expf(m1 - mn1);
        m0 = mn0; m1 = mn1;

        // P = exp(S - m), store to Ps (tf32), row sums
        float rs0 = 0.f, rs1 = 0.f;
        const int pr = w * 16 + g;
#pragma unroll
        for (int nt = 0; nt < 8; nt++) {
            const float p00 = __expf(sacc[nt][0] - m0);
            const float p01 = __expf(sacc[nt][1] - m0);
            const float p10 = __expf(sacc[nt][2] - m1);
            const float p11 = __expf(sacc[nt][3] - m1);
            rs0 += p00 + p01; rs1 += p10 + p11;
            const int pc = nt * 8 + 2 * t;
            Ps[pr * PS_STR + pc]           = f2tf32(p00);
            Ps[pr * PS_STR + pc + 1]       = f2tf32(p01);
            Ps[(pr + 8) * PS_STR + pc]     = f2tf32(p10);
            Ps[(pr + 8) * PS_STR + pc + 1] = f2tf32(p11);
        }
        rs0 += __shfl_xor_sync(0xffffffffu, rs0, 1);
        rs0 += __shfl_xor_sync(0xffffffffu, rs0, 2);
        rs1 += __shfl_xor_sync(0xffffffffu, rs1, 1);
        rs1 += __shfl_xor_sync(0xffffffffu, rs1, 2);
        l0 = l0 * cor0 + rs0;
        l1 = l1 * cor1 + rs1;
#pragma unroll
        for (int dt = 0; dt < 8; dt++) {
            oacc[dt][0] *= cor0; oacc[dt][1] *= cor0;
            oacc[dt][2] *= cor1; oacc[dt][3] *= cor1;
        }
        __syncwarp();   // Ps writes (own warp's rows) visible to own warp

        // O += P @ V
#pragma unroll
        for (int kt = 0; kt < 8; kt++) {
            uint32_t pa[4];
            pa[0] = Ps[pr * PS_STR + kt * 8 + t];
            pa[1] = Ps[(pr + 8) * PS_STR + kt * 8 + t];
            pa[2] = Ps[pr * PS_STR + kt * 8 + t + 4];
            pa[3] = Ps[(pr + 8) * PS_STR + kt * 8 + t + 4];
#pragma unroll
            for (int dt = 0; dt < 8; dt++) {
                uint32_t b[2];
                b[0] = Vs[(kt * 8 + t)     * VS_STR + dt * 8 + g];
                b[1] = Vs[(kt * 8 + t + 4) * VS_STR + dt * 8 + g];
                mma_tf32(oacc[dt], pa, b);
            }
        }
    }

    // write back into [B, L, D_MODEL]
    const int b = bh >> 4, h = bh & 15;
    const float inv0 = 1.f / l0, inv1 = 1.f / l1;
#pragma unroll
    for (int dt = 0; dt < 8; dt++) {
        const int col = h * DH + dt * 8 + 2 * t;
        float* o0 = &O[(size_t)(b * SEQ + qr)     * D_MODEL + col];
        float* o1 = &O[(size_t)(b * SEQ + qr + 8) * D_MODEL + col];
        o0[0] = oacc[dt][0] * inv0; o0[1] = oacc[dt][1] * inv0;
        o1[0] = oacc[dt][2] * inv1; o1[1] = oacc[dt][3] * inv1;
    }
}

// ---------------- launch ----------------
extern "C" void kernel_launch(void* const* d_in, const int* in_sizes, int n_in,
                              void* d_out, int out_size)
{
    const float* q  = (const float*)d_in[0];
    const float* k  = (const float*)d_in[1];
    const float* v  = (const float*)d_in[2];
    const float* Wq = (const float*)d_in[3];
    const float* bq = (const float*)d_in[4];
    const float* Wk = (const float*)d_in[5];
    const float* bk = (const float*)d_in[6];
    const float* Wv = (const float*)d_in[7];
    const float* bv = (const float*)d_in[8];
    const float* Wo = (const float*)d_in[9];
    const float* bo = (const float*)d_in[10];
    float* out = (float*)d_out;

    float *qh, *kh, *vh, *att;
    cudaGetSymbolAddress((void**)&qh,  g_qh);
    cudaGetSymbolAddress((void**)&kh,  g_kh);
    cudaGetSymbolAddress((void**)&vh,  g_vh);
    cudaGetSymbolAddress((void**)&att, g_att);

    const dim3 gemm_grid(D_MODEL / 128, M_TOTAL / 128);   // (8, 64)
    gemm_tf32<1><<<gemm_grid, 256>>>(q, Wq, bq, qh);
    gemm_tf32<1><<<gemm_grid, 256>>>(k, Wk, bk, kh);
    gemm_tf32<1><<<gemm_grid, 256>>>(v, Wv, bv, vh);

    const int smem = (64 * KS_STR + 64 * VS_STR + 128 * PS_STR) * 4;  // 70656 B
    cudaFuncSetAttribute(flash_tf32,
                         cudaFuncAttributeMaxDynamicSharedMemorySize, smem);
    flash_tf32<<<dim3(SEQ / 128, BATCH * HEADS), 256, smem>>>(qh, kh, vh, att);

    gemm_tf32<0><<<gemm_grid, 256>>>(att, Wo, bo, out);
}

// round 4
// speedup vs baseline: 3.4145x; 1.0633x over previous
#include <cuda_runtime.h>
#include <math.h>
#include <stdint.h>

#define D_MODEL 1024
#define HEADS   16
#define DH      64
#define BATCH   4
#define SEQ     2048
#define M_TOTAL (BATCH * SEQ)   // 8192

// ---------------- scratch (device globals: allocation-guard safe) ----------------
__device__ float g_qh[(size_t)BATCH * HEADS * SEQ * DH];   // [B,H,L,Dh]
__device__ float g_kh[(size_t)BATCH * HEADS * SEQ * DH];
__device__ float g_vh[(size_t)BATCH * HEADS * SEQ * DH];
__device__ float g_att[(size_t)M_TOTAL * D_MODEL];         // [B*L, D_MODEL]

// ---------------- helpers ----------------
__device__ __forceinline__ uint32_t f2tf32(float x) {
    uint32_t r;
    asm("cvt.rna.tf32.f32 %0, %1;" : "=r"(r) : "f"(x));
    return r;
}

__device__ __forceinline__ void mma_tf32(float c[4], const uint32_t a[4], const uint32_t b[2]) {
    asm("mma.sync.aligned.m16n8k8.row.col.f32.tf32.tf32.f32 "
        "{%0,%1,%2,%3}, {%4,%5,%6,%7}, {%8,%9}, {%0,%1,%2,%3};"
        : "+f"(c[0]), "+f"(c[1]), "+f"(c[2]), "+f"(c[3])
        : "r"(a[0]), "r"(a[1]), "r"(a[2]), "r"(a[3]), "r"(b[0]), "r"(b[1]));
}

// ldmatrix x4 of 8x8 b16 tiles == four 8x4 fp32 tiles; thread(g,t) gets elem [g][t]
__device__ __forceinline__ void ldsm4(uint32_t r[4], uint32_t saddr) {
    asm volatile("ldmatrix.sync.aligned.m8n8.x4.shared.b16 {%0,%1,%2,%3}, [%4];"
        : "=r"(r[0]), "=r"(r[1]), "=r"(r[2]), "=r"(r[3]) : "r"(saddr));
}

// ---------------- TF32 GEMM, double-buffered, ldmatrix A ----------------
// BM=BN=128, BK=32, 256 threads (8 warps), warp tile 64x32.
// As [2][128][36] (ldsm rows stride 9 x16B -> conflict-free), Bs [2][32][136].
#define GA_STR 36
#define GB_STR 136

template <int HEADSPLIT>
__global__ __launch_bounds__(256) void gemm_tf32(
    const float* __restrict__ A, const float* __restrict__ W,
    const float* __restrict__ bias, float* __restrict__ C)
{
    extern __shared__ uint32_t sh[];
    uint32_t* As = sh;                        // 2 * 128*36
    uint32_t* Bs = sh + 2 * 128 * GA_STR;     // 2 * 32*136

    const int tid = threadIdx.x;
    const int lane = tid & 31;
    const int w = tid >> 5;
    const int g = lane >> 2, t = lane & 3;
    const int wm = w >> 2, wn = w & 3;
    const int bm = blockIdx.y * 128, bn = blockIdx.x * 128;

    float acc[4][4][4];
#pragma unroll
    for (int mt = 0; mt < 4; mt++)
#pragma unroll
        for (int nt = 0; nt < 4; nt++)
#pragma unroll
            for (int i = 0; i < 4; i++) acc[mt][nt][i] = 0.f;

    const int arow = tid >> 1, acol = (tid & 1) * 16;   // A tile 128x32
    const int brow = tid >> 3, bcol = (tid & 7) * 16;   // B tile 32x128
    const float* Ap = A + (size_t)(bm + arow) * D_MODEL + acol;
    const float* Wp = W + (size_t)brow * D_MODEL + bn + bcol;

    // ldsm address: tile order rows[0:8)k[0:4), rows[8:16)k[0:4), rows[0:8)k[4:8), rows[8:16)k[4:8)
    const int lrow = (lane & 7) + ((lane >> 3) & 1) * 8;
    const int lcol = (lane >> 4) * 4;
    const uint32_t as_u = (uint32_t)__cvta_generic_to_shared(As);
    const uint32_t a_frag0 = as_u + (uint32_t)(((wm * 64) + lrow) * GA_STR + lcol) * 4u;

    // prologue: load tile k0=0, convert, store buf0
    float4 ra[4], rb[4];
#pragma unroll
    for (int jj = 0; jj < 4; jj++) {
        ra[jj] = *(const float4*)(Ap + jj * 4);
        rb[jj] = *(const float4*)(Wp + jj * 4);
    }
#pragma unroll
    for (int jj = 0; jj < 4; jj++) {
        uint4 ua = { f2tf32(ra[jj].x), f2tf32(ra[jj].y), f2tf32(ra[jj].z), f2tf32(ra[jj].w) };
        *(uint4*)&As[arow * GA_STR + acol + jj * 4] = ua;
        uint4 ub = { f2tf32(rb[jj].x), f2tf32(rb[jj].y), f2tf32(rb[jj].z), f2tf32(rb[jj].w) };
        *(uint4*)&Bs[brow * GB_STR + bcol + jj * 4] = ub;
    }
    __syncthreads();

    for (int k0 = 0; k0 < D_MODEL; k0 += 32) {
        const int buf = (k0 >> 5) & 1;
        const bool nxt = (k0 + 32) < D_MODEL;
        if (nxt) {
#pragma unroll
            for (int jj = 0; jj < 4; jj++) {
                ra[jj] = *(const float4*)(Ap + k0 + 32 + jj * 4);
                rb[jj] = *(const float4*)(Wp + (size_t)(k0 + 32) * D_MODEL + jj * 4);
            }
        }
        const uint32_t abase = a_frag0 + (uint32_t)(buf * 128 * GA_STR) * 4u;
        const uint32_t* Bbuf = &Bs[buf * 32 * GB_STR];
#pragma unroll
        for (int ks = 0; ks < 4; ks++) {
            const int kk = ks * 8;
            uint32_t a[4][4], b[4][2];
#pragma unroll
            for (int mt = 0; mt < 4; mt++)
                ldsm4(a[mt], abase + (uint32_t)(mt * 16 * GA_STR + kk) * 4u);
#pragma unroll
            for (int nt = 0; nt < 4; nt++) {
                const int c = wn * 32 + nt * 8 + g;
                b[nt][0] = Bbuf[(kk + t) * GB_STR + c];
                b[nt][1] = Bbuf[(kk + t + 4) * GB_STR + c];
            }
#pragma unroll
            for (int mt = 0; mt < 4; mt++)
#pragma unroll
                for (int nt = 0; nt < 4; nt++)
                    mma_tf32(acc[mt][nt], a[mt], b[nt]);
        }
        if (nxt) {
            const int nb = buf ^ 1;
#pragma unroll
            for (int jj = 0; jj < 4; jj++) {
                uint4 ua = { f2tf32(ra[jj].x), f2tf32(ra[jj].y), f2tf32(ra[jj].z), f2tf32(ra[jj].w) };
                *(uint4*)&As[nb * 128 * GA_STR + arow * GA_STR + acol + jj * 4] = ua;
                uint4 ub = { f2tf32(rb[jj].x), f2tf32(rb[jj].y), f2tf32(rb[jj].z), f2tf32(rb[jj].w) };
                *(uint4*)&Bs[nb * 32 * GB_STR + brow * GB_STR + bcol + jj * 4] = ub;
            }
        }
        __syncthreads();
    }

    // epilogue
#pragma unroll
    for (int mt = 0; mt < 4; mt++) {
#pragma unroll
        for (int nt = 0; nt < 4; nt++) {
            const int r0 = bm + wm * 64 + mt * 16 + g;
            const int c0 = bn + wn * 32 + nt * 8 + 2 * t;
#pragma unroll
            for (int i = 0; i < 4; i++) {
                const int row = r0 + (i >> 1) * 8;
                const int col = c0 + (i & 1);
                const float v = acc[mt][nt][i] + bias[col];
                if (HEADSPLIT) {
                    const int b = row >> 11, l = row & (SEQ - 1);
                    const int h = col >> 6,  d = col & 63;
                    C[(((size_t)(b * HEADS + h) * SEQ + l) << 6) + d] = v;
                } else {
                    C[(size_t)row * D_MODEL + col] = v;
                }
            }
        }
    }
}

// ---------------- TF32 flash attention: ldsm Q/K, shfl P relayout ----------------
// BQ=128, BK=64, 8 warps, warp owns 16 q-rows.
// Qs[128][68], Ks[64][68] (ldsm, stride 17x16B), Vs[64][72] (scalar frags).
#define QS_STR 68
#define KS_STR 68
#define VS_STR 72

__global__ __launch_bounds__(256) void flash_tf32(
    const float* __restrict__ Q, const float* __restrict__ K,
    const float* __restrict__ V, float* __restrict__ O)
{
    extern __shared__ uint32_t sm[];
    uint32_t* Qs = sm;                        // 128*68
    uint32_t* Ks = Qs + 128 * QS_STR;         // 64*68
    uint32_t* Vs = Ks + 64 * KS_STR;          // 64*72

    const int tid = threadIdx.x;
    const int lane = tid & 31;
    const int w = tid >> 5;
    const int g = lane >> 2, t = lane & 3;
    const int bh = blockIdx.y;
    const int bx = blockIdx.x;
    const int q0 = bx * 128;

    const float* Qb = Q + (size_t)bh * SEQ * DH;
    const float* Kb = K + (size_t)bh * SEQ * DH;
    const float* Vb = V + (size_t)bh * SEQ * DH;

    // store Q tile converted (once)
    {
        const int r = tid >> 1, cb = (tid & 1) * 32;
        const float* qp = Qb + (size_t)(q0 + r) * DH + cb;
#pragma unroll
        for (int jj = 0; jj < 8; jj++) {
            float4 v = *(const float4*)(qp + jj * 4);
            uint4 u = { f2tf32(v.x), f2tf32(v.y), f2tf32(v.z), f2tf32(v.w) };
            *(uint4*)&Qs[r * QS_STR + cb + jj * 4] = u;
        }
    }

    const uint32_t qs_u = (uint32_t)__cvta_generic_to_shared(Qs);
    const uint32_t ks_u = (uint32_t)__cvta_generic_to_shared(Ks);
    // A-frag ldsm mapping (Q)
    const int lrow = (lane & 7) + ((lane >> 3) & 1) * 8;
    const int lcol = (lane >> 4) * 4;
    const uint32_t q_frag0 = qs_u + (uint32_t)((w * 16 + lrow) * QS_STR + lcol) * 4u;
    // B-frag ldsm mapping (K): tiles (nt=2i,k0),(2i,k+4),(2i+1,k0),(2i+1,k+4)
    const int kj = lane >> 3;
    const int k_lrow = ((kj >> 1) << 3) + (lane & 7);
    const int k_lcol = (kj & 1) * 4;
    const uint32_t k_frag0 = ks_u + (uint32_t)(k_lrow * KS_STR + k_lcol) * 4u;

    float oacc[8][4];
#pragma unroll
    for (int dt = 0; dt < 8; dt++)
#pragma unroll
        for (int i = 0; i < 4; i++) oacc[dt][i] = 0.f;
    float m0 = -INFINITY, m1 = -INFINITY, l0 = 0.f, l1 = 0.f;

    const int krow = tid >> 2, kcol = (tid & 3) * 16;
    const int qr = q0 + w * 16 + g;
    const int jmax = 2 * bx + 1;

    const int src0 = (lane & 28) | (t >> 1);
    const int src2 = src0 + 2;
    const bool odd = (t & 1) != 0;

    for (int j = 0; j <= jmax; j++) {
        const int k0 = j * 64;
        __syncthreads();   // previous tile's PV done reading Ks/Vs
        const float* kp = Kb + (size_t)(k0 + krow) * DH + kcol;
        const float* vp = Vb + (size_t)(k0 + krow) * DH + kcol;
#pragma unroll
        for (int jj = 0; jj < 4; jj++) {
            float4 kv = *(const float4*)(kp + jj * 4);
            uint4 uk = { f2tf32(kv.x), f2tf32(kv.y), f2tf32(kv.z), f2tf32(kv.w) };
            *(uint4*)&Ks[krow * KS_STR + kcol + jj * 4] = uk;
            float4 vv = *(const float4*)(vp + jj * 4);
            uint4 uv = { f2tf32(vv.x), f2tf32(vv.y), f2tf32(vv.z), f2tf32(vv.w) };
            *(uint4*)&Vs[krow * VS_STR + kcol + jj * 4] = uv;
        }
        __syncthreads();

        // S = Q K^T
        float sacc[8][4];
#pragma unroll
        for (int nt = 0; nt < 8; nt++)
#pragma unroll
            for (int i = 0; i < 4; i++) sacc[nt][i] = 0.f;
#pragma unroll
        for (int kt = 0; kt < 8; kt++) {
            uint32_t qf[4];
            ldsm4(qf, q_frag0 + (uint32_t)(kt * 8) * 4u);
            uint32_t kb[8][2];
#pragma unroll
            for (int i = 0; i < 4; i++) {
                uint32_t r4[4];
                ldsm4(r4, k_frag0 + (uint32_t)(i * 16 * KS_STR + kt * 8) * 4u);
                kb[2 * i][0] = r4[0];     kb[2 * i][1] = r4[1];
                kb[2 * i + 1][0] = r4[2]; kb[2 * i + 1][1] = r4[3];
            }
#pragma unroll
            for (int nt = 0; nt < 8; nt++)
                mma_tf32(sacc[nt], qf, kb[nt]);
        }

        // scale + causal mask
        const bool need_mask = (j >= 2 * bx);
#pragma unroll
        for (int nt = 0; nt < 8; nt++) {
            const int c0 = k0 + nt * 8 + 2 * t;
#pragma unroll
            for (int i = 0; i < 4; i++) {
                sacc[nt][i] *= 0.125f;
                if (need_mask) {
                    const int row = (i >> 1) ? qr + 8 : qr;
                    const int col = c0 + (i & 1);
                    if (col > row) sacc[nt][i] = -INFINITY;
                }
            }
        }

        // online softmax
        float mt0 = -INFINITY, mt1 = -INFINITY;
#pragma unroll
        for (int nt = 0; nt < 8; nt++) {
            mt0 = fmaxf(mt0, fmaxf(sacc[nt][0], sacc[nt][1]));
            mt1 = fmaxf(mt1, fmaxf(sacc[nt][2], sacc[nt][3]));
        }
        mt0 = fmaxf(mt0, __shfl_xor_sync(0xffffffffu, mt0, 1));
        mt0 = fmaxf(mt0, __shfl_xor_sync(0xffffffffu, mt0, 2));
        mt1 = fmaxf(mt1, __shfl_xor_sync(0xffffffffu, mt1, 1));
        mt1 = fmaxf(mt1, __shfl_xor_sync(0xffffffffu, mt1, 2));

        const float mn0 = fmaxf(m0, mt0), mn1 = fmaxf(m1, mt1);
        const float cor0 = __expf(m0 - mn0), cor1 = __expf(m1 - mn1);
        m0 = mn0; m1 = mn1;

        float rs0 = 0.f, rs1 = 0.f;
#pragma unroll
        for (int nt = 0; nt < 8; nt++) {
            const float p00 = __expf(sacc[nt][0] - m0);
            const float p01 = __expf(sacc[nt][1] - m0);
            const float p10 = __expf(sacc[nt][2] - m1);
            const float p11 = __expf(sacc[nt][3] - m1);
            rs0 += p00 + p01; rs1 += p10 + p11;
            sacc[nt][0] = __uint_as_float(f2tf32(p00));
            sacc[nt][1] = __uint_as_float(f2tf32(p01));
            sacc[nt][2] = __uint_as_float(f2tf32(p10));
            sacc[nt][3] = __uint_as_float(f2tf32(p11));
        }
        rs0 += __shfl_xor_sync(0xffffffffu, rs0, 1);
        rs0 += __shfl_xor_sync(0xffffffffu, rs0, 2);
        rs1 += __shfl_xor_sync(0xffffffffu, rs1, 1);
        rs1 += __shfl_xor_sync(0xffffffffu, rs1, 2);
        l0 = l0 * cor0 + rs0;
        l1 = l1 * cor1 + rs1;
#pragma unroll
        for (int dt = 0; dt < 8; dt++) {
            oacc[dt][0] *= cor0; oacc[dt][1] *= cor0;
            oacc[dt][2] *= cor1; oacc[dt][3] *= cor1;
        }

        // O += P @ V  (P C-frag -> A-frag via intra-quad shuffles)
#pragma unroll
        for (int kt = 0; kt < 8; kt++) {
            const uint32_t u0 = __float_as_uint(sacc[kt][0]);
            const uint32_t u1 = __float_as_uint(sacc[kt][1]);
            const uint32_t u2 = __float_as_uint(sacc[kt][2]);
            const uint32_t u3 = __float_as_uint(sacc[kt][3]);
            uint32_t pa[4];
            {
                const uint32_t e0 = __shfl_sync(0xffffffffu, u0, src0);
                const uint32_t e1 = __shfl_sync(0xffffffffu, u1, src0);
                pa[0] = odd ? e1 : e0;
                const uint32_t e2 = __shfl_sync(0xffffffffu, u2, src0);
                const uint32_t e3 = __shfl_sync(0xffffffffu, u3, src0);
                pa[1] = odd ? e3 : e2;
                const uint32_t f0 = __shfl_sync(0xffffffffu, u0, src2);
                const uint32_t f1 = __shfl_sync(0xffffffffu, u1, src2);
                pa[2] = odd ? f1 : f0;
                const uint32_t f2 = __shfl_sync(0xffffffffu, u2, src2);
                const uint32_t f3 = __shfl_sync(0xffffffffu, u3, src2);
                pa[3] = odd ? f3 : f2;
            }
#pragma unroll
            for (int dt = 0; dt < 8; dt++) {
                uint32_t vb[2];
                vb[0] = Vs[(kt * 8 + t) * VS_STR + dt * 8 + g];
                vb[1] = Vs[(kt * 8 + t + 4) * VS_STR + dt * 8 + g];
                mma_tf32(oacc[dt], pa, vb);
            }
        }
    }

    // write back into [B, L, D_MODEL]
    const int b = bh >> 4, h = bh & 15;
    const float inv0 = 1.f / l0, inv1 = 1.f / l1;
#pragma unroll
    for (int dt = 0; dt < 8; dt++) {
        const int col = h * DH + dt * 8 + 2 * t;
        float* o0 = &O[(size_t)(b * SEQ + qr)     * D_MODEL + col];
        float* o1 = &O[(size_t)(b * SEQ + qr + 8) * D_MODEL + col];
        o0[0] = oacc[dt][0] * inv0; o0[1] = oacc[dt][1] * inv0;
        o1[0] = oacc[dt][2] * inv1; o1[1] = oacc[dt][3] * inv1;
    }
}

// ---------------- launch ----------------
extern "C" void kernel_launch(void* const* d_in, const int* in_sizes, int n_in,
                              void* d_out, int out_size)
{
    const float* q  = (const float*)d_in[0];
    const float* k  = (const float*)d_in[1];
    const float* v  = (const float*)d_in[2];
    const float* Wq = (const float*)d_in[3];
    const float* bq = (const float*)d_in[4];
    const float* Wk = (const float*)d_in[5];
    const float* bk = (const float*)d_in[6];
    const float* Wv = (const float*)d_in[7];
    const float* bv = (const float*)d_in[8];
    const float* Wo = (const float*)d_in[9];
    const float* bo = (const float*)d_in[10];
    float* out = (float*)d_out;

    float *qh, *kh, *vh, *att;
    cudaGetSymbolAddress((void**)&qh,  g_qh);
    cudaGetSymbolAddress((void**)&kh,  g_kh);
    cudaGetSymbolAddress((void**)&vh,  g_vh);
    cudaGetSymbolAddress((void**)&att, g_att);

    const int gemm_smem = (2 * 128 * GA_STR + 2 * 32 * GB_STR) * 4;   // 71680 B
    cudaFuncSetAttribute(gemm_tf32<1>,
                         cudaFuncAttributeMaxDynamicSharedMemorySize, gemm_smem);
    cudaFuncSetAttribute(gemm_tf32<0>,
                         cudaFuncAttributeMaxDynamicSharedMemorySize, gemm_smem);

    const dim3 gemm_grid(D_MODEL / 128, M_TOTAL / 128);   // (8, 64)
    gemm_tf32<1><<<gemm_grid, 256, gemm_smem>>>(q, Wq, bq, qh);
    gemm_tf32<1><<<gemm_grid, 256, gemm_smem>>>(k, Wk, bk, kh);
    gemm_tf32<1><<<gemm_grid, 256, gemm_smem>>>(v, Wv, bv, vh);

    const int flash_smem = (128 * QS_STR + 64 * KS_STR + 64 * VS_STR) * 4;  // 70656 B
    cudaFuncSetAttribute(flash_tf32,
                         cudaFuncAttributeMaxDynamicSharedMemorySize, flash_smem);
    flash_tf32<<<dim3(SEQ / 128, BATCH * HEADS), 256, flash_smem>>>(qh, kh, vh, att);

    gemm_tf32<0><<<gemm_grid, 256, gemm_smem>>>(att, Wo, bo, out);
}

// round 6
// speedup vs baseline: 3.4454x; 1.0091x over previous
#include <cuda_runtime.h>
#include <math.h>
#include <stdint.h>

#define D_MODEL 1024
#define HEADS   16
#define DH      64
#define BATCH   4
#define SEQ     2048
#define M_TOTAL (BATCH * SEQ)   // 8192

// ---------------- scratch (device globals: allocation-guard safe) ----------------
__device__ float g_qh[(size_t)BATCH * HEADS * SEQ * DH];   // [B,H,L,Dh]
__device__ float g_kh[(size_t)BATCH * HEADS * SEQ * DH];
__device__ float g_vh[(size_t)BATCH * HEADS * SEQ * DH];
__device__ float g_att[(size_t)M_TOTAL * D_MODEL];         // [B*L, D_MODEL]

// ---------------- helpers ----------------
__device__ __forceinline__ uint32_t f2tf32(float x) {
    uint32_t r;
    asm("cvt.rna.tf32.f32 %0, %1;" : "=r"(r) : "f"(x));
    return r;
}

__device__ __forceinline__ void mma_tf32(float c[4], const uint32_t a[4], const uint32_t b[2]) {
    asm("mma.sync.aligned.m16n8k8.row.col.f32.tf32.tf32.f32 "
        "{%0,%1,%2,%3}, {%4,%5,%6,%7}, {%8,%9}, {%0,%1,%2,%3};"
        : "+f"(c[0]), "+f"(c[1]), "+f"(c[2]), "+f"(c[3])
        : "r"(a[0]), "r"(a[1]), "r"(a[2]), "r"(a[3]), "r"(b[0]), "r"(b[1]));
}

__device__ __forceinline__ void ldsm4(uint32_t r[4], uint32_t saddr) {
    asm volatile("ldmatrix.sync.aligned.m8n8.x4.shared.b16 {%0,%1,%2,%3}, [%4];"
        : "=r"(r[0]), "=r"(r[1]), "=r"(r[2]), "=r"(r[3]) : "r"(saddr));
}

// ---------------- TF32 GEMM, double-buffered (half-staged), ldmatrix A ----------------
// BM=BN=128, BK=32, 256 threads (8 warps), warp tile 64x32, 2 CTAs/SM target.
#define GA_STR 36
#define GB_STR 136

// Batched over grid.z: selects (A,W,bias,C) per z. HEADSPLIT applies to all z.
template <int HEADSPLIT>
__global__ __launch_bounds__(256, 2) void gemm_tf32(
    const float* __restrict__ A0, const float* __restrict__ A1, const float* __restrict__ A2,
    const float* __restrict__ W0, const float* __restrict__ W1, const float* __restrict__ W2,
    const float* __restrict__ b0, const float* __restrict__ b1, const float* __restrict__ b2,
    float* __restrict__ C0, float* __restrict__ C1, float* __restrict__ C2)
{
    const int z = blockIdx.z;
    const float* A    = (z == 0) ? A0 : (z == 1) ? A1 : A2;
    const float* W    = (z == 0) ? W0 : (z == 1) ? W1 : W2;
    const float* bias = (z == 0) ? b0 : (z == 1) ? b1 : b2;
    float* C          = (z == 0) ? C0 : (z == 1) ? C1 : C2;

    extern __shared__ uint32_t sh[];
    uint32_t* As = sh;                        // 2 * 128*36
    uint32_t* Bs = sh + 2 * 128 * GA_STR;     // 2 * 32*136

    const int tid = threadIdx.x;
    const int lane = tid & 31;
    const int w = tid >> 5;
    const int g = lane >> 2, t = lane & 3;
    const int wm = w >> 2, wn = w & 3;
    const int bm = blockIdx.y * 128, bn = blockIdx.x * 128;

    float acc[4][4][4];
#pragma unroll
    for (int mt = 0; mt < 4; mt++)
#pragma unroll
        for (int nt = 0; nt < 4; nt++)
#pragma unroll
            for (int i = 0; i < 4; i++) acc[mt][nt][i] = 0.f;

    const int arow = tid >> 1, acol = (tid & 1) * 16;   // A tile 128x32
    const int brow = tid >> 3, bcol = (tid & 7) * 16;   // B tile 32x128
    const float* Ap = A + (size_t)(bm + arow) * D_MODEL + acol;
    const float* Wp = W + (size_t)brow * D_MODEL + bn + bcol;

    const int lrow = (lane & 7) + ((lane >> 3) & 1) * 8;
    const int lcol = (lane >> 4) * 4;
    const uint32_t as_u = (uint32_t)__cvta_generic_to_shared(As);
    const uint32_t a_frag0 = as_u + (uint32_t)(((wm * 64) + lrow) * GA_STR + lcol) * 4u;

    // prologue: load+convert+store tile 0 into buf0
    {
        float4 ra[4], rb[4];
#pragma unroll
        for (int jj = 0; jj < 4; jj++) {
            ra[jj] = *(const float4*)(Ap + jj * 4);
            rb[jj] = *(const float4*)(Wp + jj * 4);
        }
#pragma unroll
        for (int jj = 0; jj < 4; jj++) {
            uint4 ua = { f2tf32(ra[jj].x), f2tf32(ra[jj].y), f2tf32(ra[jj].z), f2tf32(ra[jj].w) };
            *(uint4*)&As[arow * GA_STR + acol + jj * 4] = ua;
            uint4 ub = { f2tf32(rb[jj].x), f2tf32(rb[jj].y), f2tf32(rb[jj].z), f2tf32(rb[jj].w) };
            *(uint4*)&Bs[brow * GB_STR + bcol + jj * 4] = ub;
        }
    }
    __syncthreads();

    for (int k0 = 0; k0 < D_MODEL; k0 += 32) {
        const int buf = (k0 >> 5) & 1;
        const int nb = buf ^ 1;
        const bool nxt = (k0 + 32) < D_MODEL;
        const uint32_t abase = a_frag0 + (uint32_t)(buf * 128 * GA_STR) * 4u;
        const uint32_t* Bbuf = &Bs[buf * 32 * GB_STR];
        uint32_t* Asn = &As[nb * 128 * GA_STR + arow * GA_STR + acol];
        uint32_t* Bsn = &Bs[nb * 32 * GB_STR + brow * GB_STR + bcol];

        float4 ra[2], rb[2];
        if (nxt) {
#pragma unroll
            for (int jj = 0; jj < 2; jj++) {
                ra[jj] = *(const float4*)(Ap + k0 + 32 + jj * 4);
                rb[jj] = *(const float4*)(Wp + (size_t)(k0 + 32) * D_MODEL + jj * 4);
            }
        }
#pragma unroll
        for (int ks = 0; ks < 2; ks++) {
            const int kk = ks * 8;
            uint32_t a[4][4], b[4][2];
#pragma unroll
            for (int mt = 0; mt < 4; mt++)
                ldsm4(a[mt], abase + (uint32_t)(mt * 16 * GA_STR + kk) * 4u);
#pragma unroll
            for (int nt = 0; nt < 4; nt++) {
                const int c = wn * 32 + nt * 8 + g;
                b[nt][0] = Bbuf[(kk + t) * GB_STR + c];
                b[nt][1] = Bbuf[(kk + t + 4) * GB_STR + c];
            }
#pragma unroll
            for (int mt = 0; mt < 4; mt++)
#pragma unroll
                for (int nt = 0; nt < 4; nt++)
                    mma_tf32(acc[mt][nt], a[mt], b[nt]);
        }
        if (nxt) {
#pragma unroll
            for (int jj = 0; jj < 2; jj++) {
                uint4 ua = { f2tf32(ra[jj].x), f2tf32(ra[jj].y), f2tf32(ra[jj].z), f2tf32(ra[jj].w) };
                *(uint4*)&Asn[jj * 4] = ua;
                uint4 ub = { f2tf32(rb[jj].x), f2tf32(rb[jj].y), f2tf32(rb[jj].z), f2tf32(rb[jj].w) };
                *(uint4*)&Bsn[jj * 4] = ub;
                ra[jj] = *(const float4*)(Ap + k0 + 32 + 8 + jj * 4);
                rb[jj] = *(const float4*)(Wp + (size_t)(k0 + 32) * D_MODEL + 8 + jj * 4);
            }
        }
#pragma unroll
        for (int ks = 2; ks < 4; ks++) {
            const int kk = ks * 8;
            uint32_t a[4][4], b[4][2];
#pragma unroll
            for (int mt = 0; mt < 4; mt++)
                ldsm4(a[mt], abase + (uint32_t)(mt * 16 * GA_STR + kk) * 4u);
#pragma unroll
            for (int nt = 0; nt < 4; nt++) {
                const int c = wn * 32 + nt * 8 + g;
                b[nt][0] = Bbuf[(kk + t) * GB_STR + c];
                b[nt][1] = Bbuf[(kk + t + 4) * GB_STR + c];
            }
#pragma unroll
            for (int mt = 0; mt < 4; mt++)
#pragma unroll
                for (int nt = 0; nt < 4; nt++)
                    mma_tf32(acc[mt][nt], a[mt], b[nt]);
        }
        if (nxt) {
#pragma unroll
            for (int jj = 0; jj < 2; jj++) {
                uint4 ua = { f2tf32(ra[jj].x), f2tf32(ra[jj].y), f2tf32(ra[jj].z), f2tf32(ra[jj].w) };
                *(uint4*)&Asn[8 + jj * 4] = ua;
                uint4 ub = { f2tf32(rb[jj].x), f2tf32(rb[jj].y), f2tf32(rb[jj].z), f2tf32(rb[jj].w) };
                *(uint4*)&Bsn[8 + jj * 4] = ub;
            }
        }
        __syncthreads();
    }

    // epilogue
#pragma unroll
    for (int mt = 0; mt < 4; mt++) {
#pragma unroll
        for (int nt = 0; nt < 4; nt++) {
            const int r0 = bm + wm * 64 + mt * 16 + g;
            const int c0 = bn + wn * 32 + nt * 8 + 2 * t;
#pragma unroll
            for (int i = 0; i < 4; i++) {
                const int row = r0 + (i >> 1) * 8;
                const int col = c0 + (i & 1);
                const float v = acc[mt][nt][i] + bias[col];
                if (HEADSPLIT) {
                    const int b = row >> 11, l = row & (SEQ - 1);
                    const int h = col >> 6,  d = col & 63;
                    C[(((size_t)(b * HEADS + h) * SEQ + l) << 6) + d] = v;
                } else {
                    C[(size_t)row * D_MODEL + col] = v;
                }
            }
        }
    }
}

// ---------------- TF32 flash attention: 4 warps x 32 q-rows ----------------
// BQ=128, BK=64, 128 threads. Warp owns rows [32w, 32w+32) as two m16 tiles.
#define QS_STR 68
#define KS_STR 68
#define VS_STR 72

__global__ __launch_bounds__(128, 2) void flash_tf32(
    const float* __restrict__ Q, const float* __restrict__ K,
    const float* __restrict__ V, float* __restrict__ O)
{
    extern __shared__ uint32_t sm[];
    uint32_t* Qs = sm;                        // 128*68
    uint32_t* Ks = Qs + 128 * QS_STR;         // 64*68
    uint32_t* Vs = Ks + 64 * KS_STR;          // 64*72

    const int tid = threadIdx.x;
    const int lane = tid & 31;
    const int w = tid >> 5;                  // 0..3
    const int g = lane >> 2, t = lane & 3;
    const int bh = blockIdx.y;
    const int bx = (int)(gridDim.x - 1) - (int)blockIdx.x;   // heavy tiles first
    const int q0 = bx * 128;

    const float* Qb = Q + (size_t)bh * SEQ * DH;
    const float* Kb = K + (size_t)bh * SEQ * DH;
    const float* Vb = V + (size_t)bh * SEQ * DH;

    // store Q tile converted (once): thread handles one row
    {
        const int r = tid;
        const float* qp = Qb + (size_t)(q0 + r) * DH;
#pragma unroll
        for (int jj = 0; jj < 16; jj++) {
            float4 v = *(const float4*)(qp + jj * 4);
            uint4 u = { f2tf32(v.x), f2tf32(v.y), f2tf32(v.z), f2tf32(v.w) };
            *(uint4*)&Qs[r * QS_STR + jj * 4] = u;
        }
    }

    const uint32_t qs_u = (uint32_t)__cvta_generic_to_shared(Qs);
    const uint32_t ks_u = (uint32_t)__cvta_generic_to_shared(Ks);
    const int lrow = (lane & 7) + ((lane >> 3) & 1) * 8;
    const int lcol = (lane >> 4) * 4;
    const uint32_t q_frag0 = qs_u + (uint32_t)((w * 32 + lrow) * QS_STR + lcol) * 4u;
    const int kj = lane >> 3;
    const int k_lrow = ((kj >> 1) << 3) + (lane & 7);
    const int k_lcol = (kj & 1) * 4;
    const uint32_t k_frag0 = ks_u + (uint32_t)(k_lrow * KS_STR + k_lcol) * 4u;

    float oacc[2][8][4];
#pragma unroll
    for (int mi = 0; mi < 2; mi++)
#pragma unroll
        for (int dt = 0; dt < 8; dt++)
#pragma unroll
            for (int i = 0; i < 4; i++) oacc[mi][dt][i] = 0.f;
    float mA[2] = {-INFINITY, -INFINITY}, mB[2] = {-INFINITY, -INFINITY};
    float lA[2] = {0.f, 0.f}, lB[2] = {0.f, 0.f};

    const int krow = tid >> 1, kcol = (tid & 1) * 32;
    const int qr0 = q0 + w * 32 + g;         // mi row base (sub-rows qr0+16*mi, +8)
    const int jmax = 2 * bx + 1;

    const int src0 = (lane & 28) | (t >> 1);
    const int src2 = src0 + 2;
    const bool odd = (t & 1) != 0;

    for (int j = 0; j <= jmax; j++) {
        const int k0 = j * 64;
        __syncthreads();
        const float* kp = Kb + (size_t)(k0 + krow) * DH + kcol;
        const float* vp = Vb + (size_t)(k0 + krow) * DH + kcol;
#pragma unroll
        for (int jj = 0; jj < 8; jj++) {
            float4 kv = *(const float4*)(kp + jj * 4);
            uint4 uk = { f2tf32(kv.x), f2tf32(kv.y), f2tf32(kv.z), f2tf32(kv.w) };
            *(uint4*)&Ks[krow * KS_STR + kcol + jj * 4] = uk;
            float4 vv = *(const float4*)(vp + jj * 4);
            uint4 uv = { f2tf32(vv.x), f2tf32(vv.y), f2tf32(vv.z), f2tf32(vv.w) };
            *(uint4*)&Vs[krow * VS_STR + kcol + jj * 4] = uv;
        }
        __syncthreads();

        // S = Q K^T for both 16-row tiles
        float sacc[2][8][4];
#pragma unroll
        for (int mi = 0; mi < 2; mi++)
#pragma unroll
            for (int nt = 0; nt < 8; nt++)
#pragma unroll
                for (int i = 0; i < 4; i++) sacc[mi][nt][i] = 0.f;
#pragma unroll
        for (int kt = 0; kt < 8; kt++) {
            uint32_t kb[8][2];
#pragma unroll
            for (int i = 0; i < 4; i++) {
                uint32_t r4[4];
                ldsm4(r4, k_frag0 + (uint32_t)(i * 16 * KS_STR + kt * 8) * 4u);
                kb[2 * i][0] = r4[0];     kb[2 * i][1] = r4[1];
                kb[2 * i + 1][0] = r4[2]; kb[2 * i + 1][1] = r4[3];
            }
            uint32_t qf0[4], qf1[4];
            ldsm4(qf0, q_frag0 + (uint32_t)(kt * 8) * 4u);
            ldsm4(qf1, q_frag0 + (uint32_t)(16 * QS_STR + kt * 8) * 4u);
#pragma unroll
            for (int nt = 0; nt < 8; nt++) {
                mma_tf32(sacc[0][nt], qf0, kb[nt]);
                mma_tf32(sacc[1][nt], qf1, kb[nt]);
            }
        }

        const bool need_mask = (j >= 2 * bx);
#pragma unroll
        for (int mi = 0; mi < 2; mi++) {
            const int qrm = qr0 + mi * 16;
#pragma unroll
            for (int nt = 0; nt < 8; nt++) {
                const int c0 = k0 + nt * 8 + 2 * t;
#pragma unroll
                for (int i = 0; i < 4; i++) {
                    sacc[mi][nt][i] *= 0.125f;
                    if (need_mask) {
                        const int row = (i >> 1) ? qrm + 8 : qrm;
                        const int col = c0 + (i & 1);
                        if (col > row) sacc[mi][nt][i] = -INFINITY;
                    }
                }
            }
        }

        // online softmax per mi
        float corA[2], corB[2];
#pragma unroll
        for (int mi = 0; mi < 2; mi++) {
            float mt0 = -INFINITY, mt1 = -INFINITY;
#pragma unroll
            for (int nt = 0; nt < 8; nt++) {
                mt0 = fmaxf(mt0, fmaxf(sacc[mi][nt][0], sacc[mi][nt][1]));
                mt1 = fmaxf(mt1, fmaxf(sacc[mi][nt][2], sacc[mi][nt][3]));
            }
            mt0 = fmaxf(mt0, __shfl_xor_sync(0xffffffffu, mt0, 1));
            mt0 = fmaxf(mt0, __shfl_xor_sync(0xffffffffu, mt0, 2));
            mt1 = fmaxf(mt1, __shfl_xor_sync(0xffffffffu, mt1, 1));
            mt1 = fmaxf(mt1, __shfl_xor_sync(0xffffffffu, mt1, 2));

            const float mn0 = fmaxf(mA[mi], mt0), mn1 = fmaxf(mB[mi], mt1);
            corA[mi] = __expf(mA[mi] - mn0);
            corB[mi] = __expf(mB[mi] - mn1);
            mA[mi] = mn0; mB[mi] = mn1;

            float rs0 = 0.f, rs1 = 0.f;
#pragma unroll
            for (int nt = 0; nt < 8; nt++) {
                const float p00 = __expf(sacc[mi][nt][0] - mn0);
                const float p01 = __expf(sacc[mi][nt][1] - mn0);
                const float p10 = __expf(sacc[mi][nt][2] - mn1);
                const float p11 = __expf(sacc[mi][nt][3] - mn1);
                rs0 += p00 + p01; rs1 += p10 + p11;
                sacc[mi][nt][0] = __uint_as_float(f2tf32(p00));
                sacc[mi][nt][1] = __uint_as_float(f2tf32(p01));
                sacc[mi][nt][2] = __uint_as_float(f2tf32(p10));
                sacc[mi][nt][3] = __uint_as_float(f2tf32(p11));
            }
            rs0 += __shfl_xor_sync(0xffffffffu, rs0, 1);
            rs0 += __shfl_xor_sync(0xffffffffu, rs0, 2);
            rs1 += __shfl_xor_sync(0xffffffffu, rs1, 1);
            rs1 += __shfl_xor_sync(0xffffffffu, rs1, 2);
            lA[mi] = lA[mi] * corA[mi] + rs0;
            lB[mi] = lB[mi] * corB[mi] + rs1;
#pragma unroll
            for (int dt = 0; dt < 8; dt++) {
                oacc[mi][dt][0] *= corA[mi]; oacc[mi][dt][1] *= corA[mi];
                oacc[mi][dt][2] *= corB[mi]; oacc[mi][dt][3] *= corB[mi];
            }
        }

        // O += P @ V ; V frags shared across mi
#pragma unroll
        for (int kt = 0; kt < 8; kt++) {
            uint32_t pa[2][4];
#pragma unroll
            for (int mi = 0; mi < 2; mi++) {
                const uint32_t u0 = __float_as_uint(sacc[mi][kt][0]);
                const uint32_t u1 = __float_as_uint(sacc[mi][kt][1]);
                const uint32_t u2 = __float_as_uint(sacc[mi][kt][2]);
                const uint32_t u3 = __float_as_uint(sacc[mi][kt][3]);
                const uint32_t e0 = __shfl_sync(0xffffffffu, u0, src0);
                const uint32_t e1 = __shfl_sync(0xffffffffu, u1, src0);
                pa[mi][0] = odd ? e1 : e0;
                const uint32_t e2 = __shfl_sync(0xffffffffu, u2, src0);
                const uint32_t e3 = __shfl_sync(0xffffffffu, u3, src0);
                pa[mi][1] = odd ? e3 : e2;
                const uint32_t f0 = __shfl_sync(0xffffffffu, u0, src2);
                const uint32_t f1 = __shfl_sync(0xffffffffu, u1, src2);
                pa[mi][2] = odd ? f1 : f0;
                const uint32_t f2 = __shfl_sync(0xffffffffu, u2, src2);
                const uint32_t f3 = __shfl_sync(0xffffffffu, u3, src2);
                pa[mi][3] = odd ? f3 : f2;
            }
#pragma unroll
            for (int dt = 0; dt < 8; dt++) {
                uint32_t vb[2];
                vb[0] = Vs[(kt * 8 + t) * VS_STR + dt * 8 + g];
                vb[1] = Vs[(kt * 8 + t + 4) * VS_STR + dt * 8 + g];
                mma_tf32(oacc[0][dt], pa[0], vb);
                mma_tf32(oacc[1][dt], pa[1], vb);
            }
        }
    }

    // write back into [B, L, D_MODEL]
    const int b = bh >> 4, h = bh & 15;
#pragma unroll
    for (int mi = 0; mi < 2; mi++) {
        const int qrm = qr0 + mi * 16;
        const float inv0 = 1.f / lA[mi], inv1 = 1.f / lB[mi];
#pragma unroll
        for (int dt = 0; dt < 8; dt++) {
            const int col = h * DH + dt * 8 + 2 * t;
            float* o0 = &O[(size_t)(b * SEQ + qrm)     * D_MODEL + col];
            float* o1 = &O[(size_t)(b * SEQ + qrm + 8) * D_MODEL + col];
            o0[0] = oacc[mi][dt][0] * inv0; o0[1] = oacc[mi][dt][1] * inv0;
            o1[0] = oacc[mi][dt][2] * inv1; o1[1] = oacc[mi][dt][3] * inv1;
        }
    }
}

// ---------------- launch ----------------
extern "C" void kernel_launch(void* const* d_in, const int* in_sizes, int n_in,
                              void* d_out, int out_size)
{
    const float* q  = (const float*)d_in[0];
    const float* k  = (const float*)d_in[1];
    const float* v  = (const float*)d_in[2];
    const float* Wq = (const float*)d_in[3];
    const float* bq = (const float*)d_in[4];
    const float* Wk = (const float*)d_in[5];
    const float* bk = (const float*)d_in[6];
    const float* Wv = (const float*)d_in[7];
    const float* bv = (const float*)d_in[8];
    const float* Wo = (const float*)d_in[9];
    const float* bo = (const float*)d_in[10];
    float* out = (float*)d_out;

    float *qh, *kh, *vh, *att;
    cudaGetSymbolAddress((void**)&qh,  g_qh);
    cudaGetSymbolAddress((void**)&kh,  g_kh);
    cudaGetSymbolAddress((void**)&vh,  g_vh);
    cudaGetSymbolAddress((void**)&att, g_att);

    const int gemm_smem = (2 * 128 * GA_STR + 2 * 32 * GB_STR) * 4;   // 71680 B
    cudaFuncSetAttribute(gemm_tf32<1>,
                         cudaFuncAttributeMaxDynamicSharedMemorySize, gemm_smem);
    cudaFuncSetAttribute(gemm_tf32<0>,
                         cudaFuncAttributeMaxDynamicSharedMemorySize, gemm_smem);

    // fused QKV projections: grid.z = 3
    gemm_tf32<1><<<dim3(D_MODEL / 128, M_TOTAL / 128, 3), 256, gemm_smem>>>(
        q, k, v, Wq, Wk, Wv, bq, bk, bv, qh, kh, vh);

    const int flash_smem = (128 * QS_STR + 64 * KS_STR + 64 * VS_STR) * 4;  // 70656 B
    cudaFuncSetAttribute(flash_tf32,
                         cudaFuncAttributeMaxDynamicSharedMemorySize, flash_smem);
    flash_tf32<<<dim3(SEQ / 128, BATCH * HEADS), 128, flash_smem>>>(qh, kh, vh, att);

    gemm_tf32<0><<<dim3(D_MODEL / 128, M_TOTAL / 128, 1), 256, gemm_smem>>>(
        att, att, att, Wo, Wo, Wo, bo, bo, bo, out, out, out);
}

// round 8
// speedup vs baseline: 3.6965x; 1.0729x over previous
#include <cuda_runtime.h>
#include <math.h>
#include <stdint.h>

#define D_MODEL 1024
#define HEADS   16
#define DH      64
#define BATCH   4
#define SEQ     2048
#define M_TOTAL (BATCH * SEQ)   // 8192

// ---------------- scratch (device globals: allocation-guard safe) ----------------
__device__ float g_qh[(size_t)BATCH * HEADS * SEQ * DH];   // [B,H,L,Dh] (tf32-rounded)
__device__ float g_kh[(size_t)BATCH * HEADS * SEQ * DH];
__device__ float g_vh[(size_t)BATCH * HEADS * SEQ * DH];
__device__ float g_att[(size_t)M_TOTAL * D_MODEL];         // [B*L, D_MODEL] (tf32-rounded)
__device__ float g_qc[(size_t)M_TOTAL * D_MODEL];          // pre-rounded inputs
__device__ float g_kc[(size_t)M_TOTAL * D_MODEL];
__device__ float g_vc[(size_t)M_TOTAL * D_MODEL];
__device__ float g_Wt[(size_t)4 * D_MODEL * D_MODEL];      // pre-rounded, transposed [n][k]

// ---------------- helpers ----------------
__device__ __forceinline__ uint32_t f2tf32(float x) {
    uint32_t r;
    asm("cvt.rna.tf32.f32 %0, %1;" : "=r"(r) : "f"(x));
    return r;
}

__device__ __forceinline__ uint32_t smem_u32(const void* p) {
    uint32_t a;
    asm("{ .reg .u64 t; cvta.to.shared.u64 t, %1; cvt.u32.u64 %0, t; }" : "=r"(a) : "l"(p));
    return a;
}

__device__ __forceinline__ void mma_tf32(float c[4], const uint32_t a[4], const uint32_t b[2]) {
    asm("mma.sync.aligned.m16n8k8.row.col.f32.tf32.tf32.f32 "
        "{%0,%1,%2,%3}, {%4,%5,%6,%7}, {%8,%9}, {%0,%1,%2,%3};"
        : "+f"(c[0]), "+f"(c[1]), "+f"(c[2]), "+f"(c[3])
        : "r"(a[0]), "r"(a[1]), "r"(a[2]), "r"(a[3]), "r"(b[0]), "r"(b[1]));
}

__device__ __forceinline__ void ldsm4(uint32_t r[4], uint32_t saddr) {
    asm volatile("ldmatrix.sync.aligned.m8n8.x4.shared.b16 {%0,%1,%2,%3}, [%4];"
        : "=r"(r[0]), "=r"(r[1]), "=r"(r[2]), "=r"(r[3]) : "r"(saddr));
}

#define CPA16(dst, src) asm volatile("cp.async.cg.shared.global [%0], [%1], 16;" :: "r"(dst), "l"(src))
#define CPA_COMMIT()    asm volatile("cp.async.commit_group;")
#define CPA_WAIT1()     asm volatile("cp.async.wait_group 1;")
#define CPA_WAIT0()     asm volatile("cp.async.wait_group 0;")

// ---------------- prologue converts ----------------
__global__ __launch_bounds__(256) void round_copy3(
    const float* __restrict__ a, const float* __restrict__ b, const float* __restrict__ c,
    float* __restrict__ oa, float* __restrict__ ob, float* __restrict__ oc)
{
    const int z = blockIdx.z;
    const float* in = (z == 0) ? a : (z == 1) ? b : c;
    float* out      = (z == 0) ? oa : (z == 1) ? ob : oc;
    const size_t i = ((size_t)blockIdx.x * 256 + threadIdx.x) * 4;
    float4 v = *(const float4*)(in + i);
    uint4 u = { f2tf32(v.x), f2tf32(v.y), f2tf32(v.z), f2tf32(v.w) };
    *(uint4*)(out + i) = u;
}

__global__ __launch_bounds__(256) void transpose_round4(
    const float* __restrict__ w0, const float* __restrict__ w1,
    const float* __restrict__ w2, const float* __restrict__ w3,
    float* __restrict__ outbase)
{
    const int z = blockIdx.z;
    const float* in = (z == 0) ? w0 : (z == 1) ? w1 : (z == 2) ? w2 : w3;
    float* out = outbase + (size_t)z * D_MODEL * D_MODEL;

    __shared__ float tile[32][33];
    const int tx = threadIdx.x & 31, ty = threadIdx.x >> 5;   // 32x8
    const int x = blockIdx.x * 32 + tx;
    const int y = blockIdx.y * 32 + ty;
#pragma unroll
    for (int j = 0; j < 32; j += 8)
        tile[ty + j][tx] = in[(size_t)(y + j) * D_MODEL + x];   // in[k][n]
    __syncthreads();
    const int x2 = blockIdx.y * 32 + tx;
    const int y2 = blockIdx.x * 32 + ty;
#pragma unroll
    for (int j = 0; j < 32; j += 8)
        out[(size_t)(y2 + j) * D_MODEL + x2] =
            __uint_as_float(f2tf32(tile[tx][ty + j]));          // out[n][k]
}

// ---------------- TF32 GEMM: cp.async 3-stage, ldsm A+B ----------------
// C[M,1024] = A[M,1024] @ Wt^T + bias, Wt is [N,K]. CTA 128x128, BK=32, 8 warps 64x32.
#define NSTAGE 3
#define ST_STR 36
#define ST_A_W (128 * ST_STR)
#define ST_W   (2 * ST_A_W)
#define GEMM_SMEM_B (NSTAGE * ST_W * 4)   // 110592

template <int HEADSPLIT>
__global__ __launch_bounds__(256) void gemm_cp(
    const float* __restrict__ A0, const float* __restrict__ A1, const float* __restrict__ A2,
    const float* __restrict__ T0, const float* __restrict__ T1, const float* __restrict__ T2,
    const float* __restrict__ b0, const float* __restrict__ b1, const float* __restrict__ b2,
    float* __restrict__ C0, float* __restrict__ C1, float* __restrict__ C2)
{
    const int z = blockIdx.z;
    const float* A    = (z == 0) ? A0 : (z == 1) ? A1 : A2;
    const float* Wt   = (z == 0) ? T0 : (z == 1) ? T1 : T2;
    const float* bias = (z == 0) ? b0 : (z == 1) ? b1 : b2;
    float* C          = (z == 0) ? C0 : (z == 1) ? C1 : C2;

    extern __shared__ float sh[];
    const uint32_t sbase = smem_u32(sh);
    const int tid = threadIdx.x;
    const int lane = tid & 31;
    const int w = tid >> 5;
    const int g = lane >> 2, t = lane & 3;
    const int wm = w >> 2, wn = w & 3;
    const int bm = blockIdx.y * 128, bn = blockIdx.x * 128;

    float acc[4][4][4];
#pragma unroll
    for (int mt = 0; mt < 4; mt++)
#pragma unroll
        for (int nt = 0; nt < 4; nt++)
#pragma unroll
            for (int i = 0; i < 4; i++) acc[mt][nt][i] = 0.f;

    // cp.async mapping: thread -> row tid>>1, 16-float half (tid&1), 4 chunks of 16B
    const int srow = tid >> 1;
    const int soff = (tid & 1) << 4;
    const float* Ag = A  + (size_t)(bm + srow) * D_MODEL + soff;
    const float* Bg = Wt + (size_t)(bn + srow) * D_MODEL + soff;
    const uint32_t ad0 = sbase + (uint32_t)(srow * ST_STR + soff) * 4u;
    const uint32_t bd0 = ad0 + (uint32_t)ST_A_W * 4u;

    // prologue: tiles 0,1 into stages 0,1
#pragma unroll
    for (int p = 0; p < 2; p++) {
        const int k0 = p * 32;
        const uint32_t ad = ad0 + (uint32_t)(p * ST_W) * 4u;
        const uint32_t bd = bd0 + (uint32_t)(p * ST_W) * 4u;
#pragma unroll
        for (int j = 0; j < 4; j++) CPA16(ad + j * 16, Ag + k0 + j * 4);
#pragma unroll
        for (int j = 0; j < 4; j++) CPA16(bd + j * 16, Bg + k0 + j * 4);
        CPA_COMMIT();
    }

    // fragment bases
    const int lrow = (lane & 7) + ((lane >> 3) & 1) * 8;
    const int lcol = (lane >> 4) * 4;
    const uint32_t a_frag0 = sbase + (uint32_t)(((wm * 64) + lrow) * ST_STR + lcol) * 4u;
    const int kj = lane >> 3;
    const int k_lrow = ((kj >> 1) << 3) + (lane & 7);
    const int k_lcol = (kj & 1) * 4;
    const uint32_t b_frag0 = sbase + (uint32_t)ST_A_W * 4u
                           + (uint32_t)((wn * 32 + k_lrow) * ST_STR + k_lcol) * 4u;

    int s = 0;
    for (int i = 0; i < 32; i++) {
        if (i + 1 < 32) { CPA_WAIT1(); } else { CPA_WAIT0(); }
        __syncthreads();
        if (i + 2 < 32) {
            int s2 = s + 2; if (s2 >= NSTAGE) s2 -= NSTAGE;
            const int k0 = (i + 2) * 32;
            const uint32_t ad = ad0 + (uint32_t)(s2 * ST_W) * 4u;
            const uint32_t bd = bd0 + (uint32_t)(s2 * ST_W) * 4u;
#pragma unroll
            for (int j = 0; j < 4; j++) CPA16(ad + j * 16, Ag + k0 + j * 4);
#pragma unroll
            for (int j = 0; j < 4; j++) CPA16(bd + j * 16, Bg + k0 + j * 4);
            CPA_COMMIT();
        }
        const uint32_t ab = a_frag0 + (uint32_t)(s * ST_W) * 4u;
        const uint32_t bb = b_frag0 + (uint32_t)(s * ST_W) * 4u;
#pragma unroll
        for (int ks = 0; ks < 4; ks++) {
            const int kk = ks * 8;
            uint32_t a[4][4], b[4][2];
#pragma unroll
            for (int mt = 0; mt < 4; mt++)
                ldsm4(a[mt], ab + (uint32_t)(mt * 16 * ST_STR + kk) * 4u);
#pragma unroll
            for (int h = 0; h < 2; h++) {
                uint32_t r4[4];
                ldsm4(r4, bb + (uint32_t)(h * 16 * ST_STR + kk) * 4u);
                b[2 * h][0] = r4[0];     b[2 * h][1] = r4[1];
                b[2 * h + 1][0] = r4[2]; b[2 * h + 1][1] = r4[3];
            }
#pragma unroll
            for (int mt = 0; mt < 4; mt++)
#pragma unroll
                for (int nt = 0; nt < 4; nt++)
                    mma_tf32(acc[mt][nt], a[mt], b[nt]);
        }
        if (++s == NSTAGE) s = 0;
    }

    // epilogue
#pragma unroll
    for (int mt = 0; mt < 4; mt++) {
#pragma unroll
        for (int nt = 0; nt < 4; nt++) {
            const int r0 = bm + wm * 64 + mt * 16 + g;
            const int c0 = bn + wn * 32 + nt * 8 + 2 * t;
#pragma unroll
            for (int i = 0; i < 4; i++) {
                const int row = r0 + (i >> 1) * 8;
                const int col = c0 + (i & 1);
                float v = acc[mt][nt][i] + bias[col];
                if (HEADSPLIT) {
                    v = __uint_as_float(f2tf32(v));   // pre-round for flash
                    const int b = row >> 11, l = row & (SEQ - 1);
                    const int h = col >> 6,  d = col & 63;
                    C[(((size_t)(b * HEADS + h) * SEQ + l) << 6) + d] = v;
                } else {
                    C[(size_t)row * D_MODEL + col] = v;
                }
            }
        }
    }
}

// ---------------- TF32 flash attention: cp.async staging, ldsm Q/K, shfl P ----------------
// BQ=128, BK=64, 256 threads, warp = 16 q-rows. All inputs pre-tf32-rounded.
#define QS_STR 68
#define KS_STR 68
#define VS_STR 72
#define QW (128 * QS_STR)
#define KW (64 * KS_STR)
#define VW (64 * VS_STR)
#define FLASH_SMEM_B ((QW + 2 * KW + 2 * VW) * 4)   // 106496

__global__ __launch_bounds__(256) void flash_cp(
    const float* __restrict__ Q, const float* __restrict__ K,
    const float* __restrict__ V, float* __restrict__ O)
{
    extern __shared__ uint32_t sm[];
    uint32_t* Qs = sm;                 // [128][68]
    uint32_t* Ks = Qs + QW;            // [2][64][68]
    uint32_t* Vs = Ks + 2 * KW;        // [2][64][72]

    const int tid = threadIdx.x;
    const int lane = tid & 31;
    const int w = tid >> 5;
    const int g = lane >> 2, t = lane & 3;
    const int bh = blockIdx.y;
    const int bx = blockIdx.x;
    const int q0 = bx * 128;

    const float* Qb = Q + (size_t)bh * SEQ * DH;
    const float* Kb = K + (size_t)bh * SEQ * DH;
    const float* Vb = V + (size_t)bh * SEQ * DH;

    // staging maps
    const int qrow = tid >> 1, qoff = (tid & 1) * 32;            // Q: 8 chunks/thread
    const int krow = tid >> 2, koff = (tid & 3) * 16;            // K/V: 4 chunks each
    const uint32_t qdst0 = smem_u32(Qs) + (uint32_t)(qrow * QS_STR + qoff) * 4u;
    const uint32_t kdst0 = smem_u32(Ks) + (uint32_t)(krow * KS_STR + koff) * 4u;
    const uint32_t vdst0 = smem_u32(Vs) + (uint32_t)(krow * VS_STR + koff) * 4u;
    const float* Qg = Qb + (size_t)(q0 + qrow) * DH + qoff;
    const float* Kg = Kb + (size_t)krow * DH + koff;
    const float* Vg = Vb + (size_t)krow * DH + koff;

    // prologue: Q tile + K/V tile 0 (one group)
#pragma unroll
    for (int j = 0; j < 8; j++) CPA16(qdst0 + j * 16, Qg + j * 4);
#pragma unroll
    for (int j = 0; j < 4; j++) CPA16(kdst0 + j * 16, Kg + j * 4);
#pragma unroll
    for (int j = 0; j < 4; j++) CPA16(vdst0 + j * 16, Vg + j * 4);
    CPA_COMMIT();

    const uint32_t qs_u = smem_u32(Qs);
    const uint32_t ks_u = smem_u32(Ks);
    const int lrow = (lane & 7) + ((lane >> 3) & 1) * 8;
    const int lcol = (lane >> 4) * 4;
    const uint32_t q_frag0 = qs_u + (uint32_t)((w * 16 + lrow) * QS_STR + lcol) * 4u;
    const int kj = lane >> 3;
    const int k_lrow = ((kj >> 1) << 3) + (lane & 7);
    const int k_lcol = (kj & 1) * 4;
    const uint32_t k_frag0 = ks_u + (uint32_t)(k_lrow * KS_STR + k_lcol) * 4u;

    float oacc[8][4];
#pragma unroll
    for (int dt = 0; dt < 8; dt++)
#pragma unroll
        for (int i = 0; i < 4; i++) oacc[dt][i] = 0.f;
    float m0 = -INFINITY, m1 = -INFINITY, l0 = 0.f, l1 = 0.f;

    const int qr = q0 + w * 16 + g;
    const int jmax = 2 * bx + 1;
    const int src0 = (lane & 28) | (t >> 1);
    const int src2 = src0 + 2;
    const bool odd = (t & 1) != 0;

    for (int j = 0; j <= jmax; j++) {
        CPA_WAIT0();
        __syncthreads();
        if (j + 1 <= jmax) {
            const int nb = (j + 1) & 1;
            const size_t koffg = (size_t)(j + 1) * 64 * DH;
#pragma unroll
            for (int jj = 0; jj < 4; jj++)
                CPA16(kdst0 + (uint32_t)(nb * KW) * 4u + jj * 16, Kg + koffg + jj * 4);
#pragma unroll
            for (int jj = 0; jj < 4; jj++)
                CPA16(vdst0 + (uint32_t)(nb * VW) * 4u + jj * 16, Vg + koffg + jj * 4);
            CPA_COMMIT();
        }
        const int buf = j & 1;
        const uint32_t kf = k_frag0 + (uint32_t)(buf * KW) * 4u;
        const uint32_t* Vb_s = Vs + buf * VW;
        const int k0 = j * 64;

        // S = Q K^T
        float sacc[8][4];
#pragma unroll
        for (int nt = 0; nt < 8; nt++)
#pragma unroll
            for (int i = 0; i < 4; i++) sacc[nt][i] = 0.f;
#pragma unroll
        for (int kt = 0; kt < 8; kt++) {
            uint32_t qf[4];
            ldsm4(qf, q_frag0 + (uint32_t)(kt * 8) * 4u);
            uint32_t kb[8][2];
#pragma unroll
            for (int i = 0; i < 4; i++) {
                uint32_t r4[4];
                ldsm4(r4, kf + (uint32_t)(i * 16 * KS_STR + kt * 8) * 4u);
                kb[2 * i][0] = r4[0];     kb[2 * i][1] = r4[1];
                kb[2 * i + 1][0] = r4[2]; kb[2 * i + 1][1] = r4[3];
            }
#pragma unroll
            for (int nt = 0; nt < 8; nt++)
                mma_tf32(sacc[nt], qf, kb[nt]);
        }

        const bool need_mask = (j >= 2 * bx);
#pragma unroll
        for (int nt = 0; nt < 8; nt++) {
            const int c0 = k0 + nt * 8 + 2 * t;
#pragma unroll
            for (int i = 0; i < 4; i++) {
                sacc[nt][i] *= 0.125f;
                if (need_mask) {
                    const int row = (i >> 1) ? qr + 8 : qr;
                    const int col = c0 + (i & 1);
                    if (col > row) sacc[nt][i] = -INFINITY;
                }
            }
        }

        float mt0 = -INFINITY, mt1 = -INFINITY;
#pragma unroll
        for (int nt = 0; nt < 8; nt++) {
            mt0 = fmaxf(mt0, fmaxf(sacc[nt][0], sacc[nt][1]));
            mt1 = fmaxf(mt1, fmaxf(sacc[nt][2], sacc[nt][3]));
        }
        mt0 = fmaxf(mt0, __shfl_xor_sync(0xffffffffu, mt0, 1));
        mt0 = fmaxf(mt0, __shfl_xor_sync(0xffffffffu, mt0, 2));
        mt1 = fmaxf(mt1, __shfl_xor_sync(0xffffffffu, mt1, 1));
        mt1 = fmaxf(mt1, __shfl_xor_sync(0xffffffffu, mt1, 2));

        const float mn0 = fmaxf(m0, mt0), mn1 = fmaxf(m1, mt1);
        const float cor0 = __expf(m0 - mn0), cor1 = __expf(m1 - mn1);
        m0 = mn0; m1 = mn1;

        float rs0 = 0.f, rs1 = 0.f;
#pragma unroll
        for (int nt = 0; nt < 8; nt++) {
            const float p00 = __expf(sacc[nt][0] - m0);
            const float p01 = __expf(sacc[nt][1] - m0);
            const float p10 = __expf(sacc[nt][2] - m1);
            const float p11 = __expf(sacc[nt][3] - m1);
            rs0 += p00 + p01; rs1 += p10 + p11;
            sacc[nt][0] = __uint_as_float(f2tf32(p00));
            sacc[nt][1] = __uint_as_float(f2tf32(p01));
            sacc[nt][2] = __uint_as_float(f2tf32(p10));
            sacc[nt][3] = __uint_as_float(f2tf32(p11));
        }
        rs0 += __shfl_xor_sync(0xffffffffu, rs0, 1);
        rs0 += __shfl_xor_sync(0xffffffffu, rs0, 2);
        rs1 += __shfl_xor_sync(0xffffffffu, rs1, 1);
        rs1 += __shfl_xor_sync(0xffffffffu, rs1, 2);
        l0 = l0 * cor0 + rs0;
        l1 = l1 * cor1 + rs1;
#pragma unroll
        for (int dt = 0; dt < 8; dt++) {
            oacc[dt][0] *= cor0; oacc[dt][1] *= cor0;
            oacc[dt][2] *= cor1; oacc[dt][3] *= cor1;
        }

        // O += P @ V  (P relayout via intra-quad shuffles)
#pragma unroll
        for (int kt = 0; kt < 8; kt++) {
            const uint32_t u0 = __float_as_uint(sacc[kt][0]);
            const uint32_t u1 = __float_as_uint(sacc[kt][1]);
            const uint32_t u2 = __float_as_uint(sacc[kt][2]);
            const uint32_t u3 = __float_as_uint(sacc[kt][3]);
            uint32_t pa[4];
            {
                const uint32_t e0 = __shfl_sync(0xffffffffu, u0, src0);
                const uint32_t e1 = __shfl_sync(0xffffffffu, u1, src0);
                pa[0] = odd ? e1 : e0;
                const uint32_t e2 = __shfl_sync(0xffffffffu, u2, src0);
                const uint32_t e3 = __shfl_sync(0xffffffffu, u3, src0);
                pa[1] = odd ? e3 : e2;
                const uint32_t f0 = __shfl_sync(0xffffffffu, u0, src2);
                const uint32_t f1 = __shfl_sync(0xffffffffu, u1, src2);
                pa[2] = odd ? f1 : f0;
                const uint32_t f2 = __shfl_sync(0xffffffffu, u2, src2);
                const uint32_t f3 = __shfl_sync(0xffffffffu, u3, src2);
                pa[3] = odd ? f3 : f2;
            }
#pragma unroll
            for (int dt = 0; dt < 8; dt++) {
                uint32_t vb[2];
                vb[0] = Vb_s[(kt * 8 + t) * VS_STR + dt * 8 + g];
                vb[1] = Vb_s[(kt * 8 + t + 4) * VS_STR + dt * 8 + g];
                mma_tf32(oacc[dt], pa, vb);
            }
        }
    }

    // write back into [B, L, D_MODEL], pre-rounded for GEMM-2
    const int b = bh >> 4, h = bh & 15;
    const float inv0 = 1.f / l0, inv1 = 1.f / l1;
#pragma unroll
    for (int dt = 0; dt < 8; dt++) {
        const int col = h * DH + dt * 8 + 2 * t;
        float* o0 = &O[(size_t)(b * SEQ + qr)     * D_MODEL + col];
        float* o1 = &O[(size_t)(b * SEQ + qr + 8) * D_MODEL + col];
        o0[0] = __uint_as_float(f2tf32(oacc[dt][0] * inv0));
        o0[1] = __uint_as_float(f2tf32(oacc[dt][1] * inv0));
        o1[0] = __uint_as_float(f2tf32(oacc[dt][2] * inv1));
        o1[1] = __uint_as_float(f2tf32(oacc[dt][3] * inv1));
    }
}

// ---------------- launch ----------------
extern "C" void kernel_launch(void* const* d_in, const int* in_sizes, int n_in,
                              void* d_out, int out_size)
{
    const float* q  = (const float*)d_in[0];
    const float* k  = (const float*)d_in[1];
    const float* v  = (const float*)d_in[2];
    const float* Wq = (const float*)d_in[3];
    const float* bq = (const float*)d_in[4];
    const float* Wk = (const float*)d_in[5];
    const float* bk = (const float*)d_in[6];
    const float* Wv = (const float*)d_in[7];
    const float* bv = (const float*)d_in[8];
    const float* Wo = (const float*)d_in[9];
    const float* bo = (const float*)d_in[10];
    float* out = (float*)d_out;

    float *qh, *kh, *vh, *att, *qc, *kc, *vc, *Wt;
    cudaGetSymbolAddress((void**)&qh,  g_qh);
    cudaGetSymbolAddress((void**)&kh,  g_kh);
    cudaGetSymbolAddress((void**)&vh,  g_vh);
    cudaGetSymbolAddress((void**)&att, g_att);
    cudaGetSymbolAddress((void**)&qc,  g_qc);
    cudaGetSymbolAddress((void**)&kc,  g_kc);
    cudaGetSymbolAddress((void**)&vc,  g_vc);
    cudaGetSymbolAddress((void**)&Wt,  g_Wt);

    // prologue converts
    round_copy3<<<dim3(M_TOTAL * D_MODEL / (256 * 4), 1, 3), 256>>>(q, k, v, qc, kc, vc);
    transpose_round4<<<dim3(32, 32, 4), 256>>>(Wq, Wk, Wv, Wo, Wt);

    cudaFuncSetAttribute(gemm_cp<1>,
                         cudaFuncAttributeMaxDynamicSharedMemorySize, GEMM_SMEM_B);
    cudaFuncSetAttribute(gemm_cp<0>,
                         cudaFuncAttributeMaxDynamicSharedMemorySize, GEMM_SMEM_B);
    cudaFuncSetAttribute(flash_cp,
                         cudaFuncAttributeMaxDynamicSharedMemorySize, FLASH_SMEM_B);

    const size_t WSZ = (size_t)D_MODEL * D_MODEL;
    gemm_cp<1><<<dim3(D_MODEL / 128, M_TOTAL / 128, 3), 256, GEMM_SMEM_B>>>(
        qc, kc, vc, Wt, Wt + WSZ, Wt + 2 * WSZ, bq, bk, bv, qh, kh, vh);

    flash_cp<<<dim3(SEQ / 128, BATCH * HEADS), 256, FLASH_SMEM_B>>>(qh, kh, vh, att);

    gemm_cp<0><<<dim3(D_MODEL / 128, M_TOTAL / 128, 1), 256, GEMM_SMEM_B>>>(
        att, att, att, Wt + 3 * WSZ, Wt + 3 * WSZ, Wt + 3 * WSZ,
        bo, bo, bo, out, out, out);
}

// round 9
// speedup vs baseline: 6.8849x; 1.8626x over previous
#include <cuda_runtime.h>
#include <cuda_fp16.h>
#include <math.h>
#include <stdint.h>

#define D_MODEL 1024
#define HEADS   16
#define DH      64
#define BATCH   4
#define SEQ     2048
#define M_TOTAL (BATCH * SEQ)   // 8192

// ---------------- scratch (device globals: allocation-guard safe) ----------------
__device__ __half g_qh[(size_t)BATCH * HEADS * SEQ * DH];   // [B,H,L,Dh] fp16
__device__ __half g_kh[(size_t)BATCH * HEADS * SEQ * DH];
__device__ __half g_vh[(size_t)BATCH * HEADS * SEQ * DH];
__device__ __half g_att[(size_t)M_TOTAL * D_MODEL];         // [B*L, D_MODEL] fp16
__device__ __half g_qc[(size_t)M_TOTAL * D_MODEL];          // fp16 inputs
__device__ __half g_kc[(size_t)M_TOTAL * D_MODEL];
__device__ __half g_vc[(size_t)M_TOTAL * D_MODEL];
__device__ __half g_Wt[(size_t)4 * D_MODEL * D_MODEL];      // fp16, transposed [n][k]

// ---------------- helpers ----------------
__device__ __forceinline__ uint32_t smem_u32(const void* p) {
    uint32_t a;
    asm("{ .reg .u64 t; cvta.to.shared.u64 t, %1; cvt.u32.u64 %0, t; }" : "=r"(a) : "l"(p));
    return a;
}

__device__ __forceinline__ uint32_t pack_h2(float lo, float hi) {
    uint32_t r;
    asm("cvt.rn.f16x2.f32 %0, %1, %2;" : "=r"(r) : "f"(hi), "f"(lo));
    return r;
}

__device__ __forceinline__ void mma_f16(float c[4], const uint32_t a[4], const uint32_t b[2]) {
    asm("mma.sync.aligned.m16n8k16.row.col.f32.f16.f16.f32 "
        "{%0,%1,%2,%3}, {%4,%5,%6,%7}, {%8,%9}, {%0,%1,%2,%3};"
        : "+f"(c[0]), "+f"(c[1]), "+f"(c[2]), "+f"(c[3])
        : "r"(a[0]), "r"(a[1]), "r"(a[2]), "r"(a[3]), "r"(b[0]), "r"(b[1]));
}

__device__ __forceinline__ void ldsm4(uint32_t r[4], uint32_t saddr) {
    asm volatile("ldmatrix.sync.aligned.m8n8.x4.shared.b16 {%0,%1,%2,%3}, [%4];"
        : "=r"(r[0]), "=r"(r[1]), "=r"(r[2]), "=r"(r[3]) : "r"(saddr));
}

__device__ __forceinline__ void ldsm4t(uint32_t r[4], uint32_t saddr) {
    asm volatile("ldmatrix.sync.aligned.m8n8.x4.trans.shared.b16 {%0,%1,%2,%3}, [%4];"
        : "=r"(r[0]), "=r"(r[1]), "=r"(r[2]), "=r"(r[3]) : "r"(saddr));
}

#define CPA16(dst, src) asm volatile("cp.async.cg.shared.global [%0], [%1], 16;" :: "r"(dst), "l"(src))
#define CPA_COMMIT()    asm volatile("cp.async.commit_group;")
#define CPA_WAIT1()     asm volatile("cp.async.wait_group 1;")
#define CPA_WAIT0()     asm volatile("cp.async.wait_group 0;")

// ---------------- prologue converts ----------------
__global__ __launch_bounds__(256) void tohalf3(
    const float* __restrict__ a, const float* __restrict__ b, const float* __restrict__ c,
    __half* __restrict__ oa, __half* __restrict__ ob, __half* __restrict__ oc)
{
    const int z = blockIdx.z;
    const float* in = (z == 0) ? a : (z == 1) ? b : c;
    __half* out     = (z == 0) ? oa : (z == 1) ? ob : oc;
    const size_t i = ((size_t)blockIdx.x * 256 + threadIdx.x) * 4;
    float4 v = *(const float4*)(in + i);
    uint2 u = { pack_h2(v.x, v.y), pack_h2(v.z, v.w) };
    *(uint2*)(out + i) = u;
}

__global__ __launch_bounds__(256) void transpose_half4(
    const float* __restrict__ w0, const float* __restrict__ w1,
    const float* __restrict__ w2, const float* __restrict__ w3,
    __half* __restrict__ outbase)
{
    const int z = blockIdx.z;
    const float* in = (z == 0) ? w0 : (z == 1) ? w1 : (z == 2) ? w2 : w3;
    __half* out = outbase + (size_t)z * D_MODEL * D_MODEL;

    __shared__ float tile[32][33];
    const int tx = threadIdx.x & 31, ty = threadIdx.x >> 5;   // 32x8
    const int x = blockIdx.x * 32 + tx;
    const int y = blockIdx.y * 32 + ty;
#pragma unroll
    for (int j = 0; j < 32; j += 8)
        tile[ty + j][tx] = in[(size_t)(y + j) * D_MODEL + x];   // in[k][n]
    __syncthreads();
    const int x2 = blockIdx.y * 32 + tx;
    const int y2 = blockIdx.x * 32 + ty;
#pragma unroll
    for (int j = 0; j < 32; j += 8)
        out[(size_t)(y2 + j) * D_MODEL + x2] = __float2half_rn(tile[tx][ty + j]);  // out[n][k]
}

// ---------------- FP16 GEMM: cp.async 3-stage, ldsm A+B ----------------
// C[M,1024] = A[M,1024] @ Wt^T + bias, Wt is [N,K] fp16. CTA 128x128, BK=64, 8 warps 64x32.
#define NSTAGE 3
#define SSTR 72                       // fp16 units per row (64 data + 8 pad) = 144B
#define ST_HALF (128 * SSTR)          // fp16 per matrix per stage
#define STAGE_B (2 * ST_HALF * 2)     // bytes per stage (A+B) = 36864
#define GEMM_SMEM_B (NSTAGE * STAGE_B)  // 110592

template <int HEADSPLIT>
__global__ __launch_bounds__(256) void gemm_fp16(
    const __half* __restrict__ A0, const __half* __restrict__ A1, const __half* __restrict__ A2,
    const __half* __restrict__ T0, const __half* __restrict__ T1, const __half* __restrict__ T2,
    const float* __restrict__ b0, const float* __restrict__ b1, const float* __restrict__ b2,
    void* __restrict__ C0, void* __restrict__ C1, void* __restrict__ C2)
{
    const int z = blockIdx.z;
    const __half* A   = (z == 0) ? A0 : (z == 1) ? A1 : A2;
    const __half* Wt  = (z == 0) ? T0 : (z == 1) ? T1 : T2;
    const float* bias = (z == 0) ? b0 : (z == 1) ? b1 : b2;
    void* C           = (z == 0) ? C0 : (z == 1) ? C1 : C2;

    extern __shared__ __half sh[];
    const uint32_t sbase = smem_u32(sh);
    const int tid = threadIdx.x;
    const int lane = tid & 31;
    const int w = tid >> 5;
    const int g = lane >> 2, t = lane & 3;
    const int wm = w >> 2, wn = w & 3;
    const int bm = blockIdx.y * 128, bn = blockIdx.x * 128;

    float acc[4][4][4];
#pragma unroll
    for (int mt = 0; mt < 4; mt++)
#pragma unroll
        for (int nt = 0; nt < 4; nt++)
#pragma unroll
            for (int i = 0; i < 4; i++) acc[mt][nt][i] = 0.f;

    // cp.async: thread -> row tid>>1, 32-fp16 half (tid&1), 4 chunks of 16B
    const int srow = tid >> 1;
    const int soff = (tid & 1) << 5;
    const __half* Ag = A  + (size_t)(bm + srow) * D_MODEL + soff;
    const __half* Bg = Wt + (size_t)(bn + srow) * D_MODEL + soff;
    const uint32_t ad0 = sbase + (uint32_t)(srow * SSTR + soff) * 2u;
    const uint32_t bd0 = ad0 + (uint32_t)ST_HALF * 2u;

    // prologue: tiles 0,1 into stages 0,1
#pragma unroll
    for (int p = 0; p < 2; p++) {
        const int k0 = p * 64;
        const uint32_t ad = ad0 + (uint32_t)(p * STAGE_B);
        const uint32_t bd = bd0 + (uint32_t)(p * STAGE_B);
#pragma unroll
        for (int j = 0; j < 4; j++) CPA16(ad + j * 16, Ag + k0 + j * 8);
#pragma unroll
        for (int j = 0; j < 4; j++) CPA16(bd + j * 16, Bg + k0 + j * 8);
        CPA_COMMIT();
    }

    // fragment bases
    const int lrow = (lane & 7) + ((lane >> 3) & 1) * 8;
    const int alcol = (lane >> 4) * 8;
    const uint32_t a_frag0 = sbase + (uint32_t)(((wm * 64) + lrow) * SSTR + alcol) * 2u;
    const int bn_lane = (lane & 7) + (lane >> 4) * 8;
    const int k_lane = ((lane >> 3) & 1) * 8;
    const uint32_t b_frag0 = sbase + (uint32_t)ST_HALF * 2u
                           + (uint32_t)((wn * 32 + bn_lane) * SSTR + k_lane) * 2u;

    int s = 0;
    for (int i = 0; i < 16; i++) {
        if (i + 1 < 16) { CPA_WAIT1(); } else { CPA_WAIT0(); }
        __syncthreads();
        if (i + 2 < 16) {
            int s2 = s + 2; if (s2 >= NSTAGE) s2 -= NSTAGE;
            const int k0 = (i + 2) * 64;
            const uint32_t ad = ad0 + (uint32_t)(s2 * STAGE_B);
            const uint32_t bd = bd0 + (uint32_t)(s2 * STAGE_B);
#pragma unroll
            for (int j = 0; j < 4; j++) CPA16(ad + j * 16, Ag + k0 + j * 8);
#pragma unroll
            for (int j = 0; j < 4; j++) CPA16(bd + j * 16, Bg + k0 + j * 8);
            CPA_COMMIT();
        }
        const uint32_t ab = a_frag0 + (uint32_t)(s * STAGE_B);
        const uint32_t bb = b_frag0 + (uint32_t)(s * STAGE_B);
#pragma unroll
        for (int ks = 0; ks < 4; ks++) {
            uint32_t a[4][4], b[4][2];
#pragma unroll
            for (int mt = 0; mt < 4; mt++)
                ldsm4(a[mt], ab + (uint32_t)(mt * 16 * SSTR) * 2u + ks * 32);
#pragma unroll
            for (int p = 0; p < 2; p++) {
                uint32_t r4[4];
                ldsm4(r4, bb + (uint32_t)(p * 16 * SSTR) * 2u + ks * 32);
                b[2 * p][0] = r4[0];     b[2 * p][1] = r4[1];
                b[2 * p + 1][0] = r4[2]; b[2 * p + 1][1] = r4[3];
            }
#pragma unroll
            for (int mt = 0; mt < 4; mt++)
#pragma unroll
                for (int nt = 0; nt < 4; nt++)
                    mma_f16(acc[mt][nt], a[mt], b[nt]);
        }
        if (++s == NSTAGE) s = 0;
    }

    // epilogue
#pragma unroll
    for (int mt = 0; mt < 4; mt++) {
#pragma unroll
        for (int nt = 0; nt < 4; nt++) {
            const int r0 = bm + wm * 64 + mt * 16 + g;
            const int c0 = bn + wn * 32 + nt * 8 + 2 * t;
#pragma unroll
            for (int i = 0; i < 4; i++) {
                const int row = r0 + (i >> 1) * 8;
                const int col = c0 + (i & 1);
                const float v = acc[mt][nt][i] + bias[col];
                if (HEADSPLIT) {
                    const int b = row >> 11, l = row & (SEQ - 1);
                    const int h = col >> 6,  d = col & 63;
                    ((__half*)C)[(((size_t)(b * HEADS + h) * SEQ + l) << 6) + d] =
                        __float2half_rn(v);
                } else {
                    ((float*)C)[(size_t)row * D_MODEL + col] = v;
                }
            }
        }
    }
}

// ---------------- FP16 flash attention: cp.async, ldsm Q/K, ldsm.trans V ----------------
// BQ=128, BK=64, 256 threads, warp = 16 q-rows.
#define FSTR 72
#define QB_BYTES (128 * FSTR * 2)    // 18432
#define KB_BYTES (64 * FSTR * 2)     // 9216
#define FLASH_SMEM_B (QB_BYTES + 4 * KB_BYTES)  // 55296

__global__ __launch_bounds__(256) void flash_fp16(
    const __half* __restrict__ Q, const __half* __restrict__ K,
    const __half* __restrict__ V, __half* __restrict__ O)
{
    extern __shared__ __half sm[];
    const uint32_t sbase = smem_u32(sm);
    const uint32_t kbase = sbase + QB_BYTES;
    const uint32_t vbase = kbase + 2 * KB_BYTES;

    const int tid = threadIdx.x;
    const int lane = tid & 31;
    const int w = tid >> 5;
    const int g = lane >> 2, t = lane & 3;
    const int bh = blockIdx.y;
    const int bx = blockIdx.x;
    const int q0 = bx * 128;

    const __half* Qb = Q + (size_t)bh * SEQ * DH;
    const __half* Kb = K + (size_t)bh * SEQ * DH;
    const __half* Vb = V + (size_t)bh * SEQ * DH;

    // staging maps
    const int qrow = tid >> 1, qoff = (tid & 1) * 32;   // Q: 4 chunks of 16B
    const int krow = tid >> 2, koff = (tid & 3) * 16;   // K/V: 2 chunks of 16B
    const uint32_t qdst0 = sbase + (uint32_t)(qrow * FSTR + qoff) * 2u;
    const uint32_t kdst0 = kbase + (uint32_t)(krow * FSTR + koff) * 2u;
    const uint32_t vdst0 = vbase + (uint32_t)(krow * FSTR + koff) * 2u;
    const __half* Qg = Qb + (size_t)(q0 + qrow) * DH + qoff;
    const __half* Kg = Kb + (size_t)krow * DH + koff;
    const __half* Vg = Vb + (size_t)krow * DH + koff;

    // prologue: Q tile + K/V tile 0
#pragma unroll
    for (int j = 0; j < 4; j++) CPA16(qdst0 + j * 16, Qg + j * 8);
#pragma unroll
    for (int j = 0; j < 2; j++) CPA16(kdst0 + j * 16, Kg + j * 8);
#pragma unroll
    for (int j = 0; j < 2; j++) CPA16(vdst0 + j * 16, Vg + j * 8);
    CPA_COMMIT();

    // fragment bases
    const int lrow = (lane & 7) + ((lane >> 3) & 1) * 8;
    const uint32_t q_frag0 = sbase + (uint32_t)((w * 16 + lrow) * FSTR + (lane >> 4) * 8) * 2u;
    const int bn_lane = (lane & 7) + (lane >> 4) * 8;
    const int k_lane = ((lane >> 3) & 1) * 8;
    const uint32_t k_frag0 = kbase + (uint32_t)(bn_lane * FSTR + k_lane) * 2u;
    const int vrow_lane = (lane & 7) + ((lane >> 3) & 1) * 8;
    const int vcol_lane = (lane >> 4) * 8;
    const uint32_t v_frag0 = vbase + (uint32_t)(vrow_lane * FSTR + vcol_lane) * 2u;

    float oacc[8][4];
#pragma unroll
    for (int dt = 0; dt < 8; dt++)
#pragma unroll
        for (int i = 0; i < 4; i++) oacc[dt][i] = 0.f;
    float m0 = -INFINITY, m1 = -INFINITY, l0 = 0.f, l1 = 0.f;

    const int qr = q0 + w * 16 + g;
    const int jmax = 2 * bx + 1;

    for (int j = 0; j <= jmax; j++) {
        CPA_WAIT0();
        __syncthreads();
        if (j + 1 <= jmax) {
            const int nb = (j + 1) & 1;
            const size_t koffg = (size_t)(j + 1) * 64 * DH;
#pragma unroll
            for (int jj = 0; jj < 2; jj++)
                CPA16(kdst0 + (uint32_t)(nb * KB_BYTES) + jj * 16, Kg + koffg + jj * 8);
#pragma unroll
            for (int jj = 0; jj < 2; jj++)
                CPA16(vdst0 + (uint32_t)(nb * KB_BYTES) + jj * 16, Vg + koffg + jj * 8);
            CPA_COMMIT();
        }
        const int buf = j & 1;
        const uint32_t kf = k_frag0 + (uint32_t)(buf * KB_BYTES);
        const uint32_t vf = v_frag0 + (uint32_t)(buf * KB_BYTES);
        const int k0 = j * 64;

        // S = Q K^T
        float sacc[8][4];
#pragma unroll
        for (int nt = 0; nt < 8; nt++)
#pragma unroll
            for (int i = 0; i < 4; i++) sacc[nt][i] = 0.f;
#pragma unroll
        for (int kt = 0; kt < 4; kt++) {
            uint32_t qf[4];
            ldsm4(qf, q_frag0 + kt * 32);
            uint32_t kb[8][2];
#pragma unroll
            for (int p = 0; p < 4; p++) {
                uint32_t r4[4];
                ldsm4(r4, kf + (uint32_t)(p * 16 * FSTR) * 2u + kt * 32);
                kb[2 * p][0] = r4[0];     kb[2 * p][1] = r4[1];
                kb[2 * p + 1][0] = r4[2]; kb[2 * p + 1][1] = r4[3];
            }
#pragma unroll
            for (int nt = 0; nt < 8; nt++)
                mma_f16(sacc[nt], qf, kb[nt]);
        }

        // scale + causal mask
        const bool need_mask = (j >= 2 * bx);
#pragma unroll
        for (int nt = 0; nt < 8; nt++) {
            const int c0 = k0 + nt * 8 + 2 * t;
#pragma unroll
            for (int i = 0; i < 4; i++) {
                sacc[nt][i] *= 0.125f;
                if (need_mask) {
                    const int row = (i >> 1) ? qr + 8 : qr;
                    const int col = c0 + (i & 1);
                    if (col > row) sacc[nt][i] = -INFINITY;
                }
            }
        }

        // online softmax
        float mt0 = -INFINITY, mt1 = -INFINITY;
#pragma unroll
        for (int nt = 0; nt < 8; nt++) {
            mt0 = fmaxf(mt0, fmaxf(sacc[nt][0], sacc[nt][1]));
            mt1 = fmaxf(mt1, fmaxf(sacc[nt][2], sacc[nt][3]));
        }
        mt0 = fmaxf(mt0, __shfl_xor_sync(0xffffffffu, mt0, 1));
        mt0 = fmaxf(mt0, __shfl_xor_sync(0xffffffffu, mt0, 2));
        mt1 = fmaxf(mt1, __shfl_xor_sync(0xffffffffu, mt1, 1));
        mt1 = fmaxf(mt1, __shfl_xor_sync(0xffffffffu, mt1, 2));

        const float mn0 = fmaxf(m0, mt0), mn1 = fmaxf(m1, mt1);
        const float cor0 = __expf(m0 - mn0), cor1 = __expf(m1 - mn1);
        m0 = mn0; m1 = mn1;

        float rs0 = 0.f, rs1 = 0.f;
#pragma unroll
        for (int nt = 0; nt < 8; nt++) {
            const float p00 = __expf(sacc[nt][0] - m0);
            const float p01 = __expf(sacc[nt][1] - m0);
            const float p10 = __expf(sacc[nt][2] - m1);
            const float p11 = __expf(sacc[nt][3] - m1);
            rs0 += p00 + p01; rs1 += p10 + p11;
            sacc[nt][0] = p00; sacc[nt][1] = p01;
            sacc[nt][2] = p10; sacc[nt][3] = p11;
        }
        rs0 += __shfl_xor_sync(0xffffffffu, rs0, 1);
        rs0 += __shfl_xor_sync(0xffffffffu, rs0, 2);
        rs1 += __shfl_xor_sync(0xffffffffu, rs1, 1);
        rs1 += __shfl_xor_sync(0xffffffffu, rs1, 2);
        l0 = l0 * cor0 + rs0;
        l1 = l1 * cor1 + rs1;
#pragma unroll
        for (int dt = 0; dt < 8; dt++) {
            oacc[dt][0] *= cor0; oacc[dt][1] *= cor0;
            oacc[dt][2] *= cor1; oacc[dt][3] *= cor1;
        }

        // O += P @ V  (P C-frag packs directly into fp16 A-frag; V via ldsm.trans)
#pragma unroll
        for (int kt2 = 0; kt2 < 4; kt2++) {
            uint32_t pa[4];
            pa[0] = pack_h2(sacc[2 * kt2][0],     sacc[2 * kt2][1]);
            pa[1] = pack_h2(sacc[2 * kt2][2],     sacc[2 * kt2][3]);
            pa[2] = pack_h2(sacc[2 * kt2 + 1][0], sacc[2 * kt2 + 1][1]);
            pa[3] = pack_h2(sacc[2 * kt2 + 1][2], sacc[2 * kt2 + 1][3]);
#pragma unroll
            for (int pd = 0; pd < 4; pd++) {
                uint32_t r4[4];
                ldsm4t(r4, vf + (uint32_t)(kt2 * 16 * FSTR + pd * 16) * 2u);
                uint32_t vb0[2] = { r4[0], r4[1] };
                uint32_t vb1[2] = { r4[2], r4[3] };
                mma_f16(oacc[2 * pd],     pa, vb0);
                mma_f16(oacc[2 * pd + 1], pa, vb1);
            }
        }
    }

    // write back into [B, L, D_MODEL] as fp16
    const int b = bh >> 4, h = bh & 15;
    const float inv0 = 1.f / l0, inv1 = 1.f / l1;
#pragma unroll
    for (int dt = 0; dt < 8; dt++) {
        const int col = h * DH + dt * 8 + 2 * t;
        __half* o0 = &O[(size_t)(b * SEQ + qr)     * D_MODEL + col];
        __half* o1 = &O[(size_t)(b * SEQ + qr + 8) * D_MODEL + col];
        *(uint32_t*)o0 = pack_h2(oacc[dt][0] * inv0, oacc[dt][1] * inv0);
        *(uint32_t*)o1 = pack_h2(oacc[dt][2] * inv1, oacc[dt][3] * inv1);
    }
}

// ---------------- launch ----------------
extern "C" void kernel_launch(void* const* d_in, const int* in_sizes, int n_in,
                              void* d_out, int out_size)
{
    const float* q  = (const float*)d_in[0];
    const float* k  = (const float*)d_in[1];
    const float* v  = (const float*)d_in[2];
    const float* Wq = (const float*)d_in[3];
    const float* bq = (const float*)d_in[4];
    const float* Wk = (const float*)d_in[5];
    const float* bk = (const float*)d_in[6];
    const float* Wv = (const float*)d_in[7];
    const float* bv = (const float*)d_in[8];
    const float* Wo = (const float*)d_in[9];
    const float* bo = (const float*)d_in[10];
    float* out = (float*)d_out;

    __half *qh, *kh, *vh, *att, *qc, *kc, *vc, *Wt;
    cudaGetSymbolAddress((void**)&qh,  g_qh);
    cudaGetSymbolAddress((void**)&kh,  g_kh);
    cudaGetSymbolAddress((void**)&vh,  g_vh);
    cudaGetSymbolAddress((void**)&att, g_att);
    cudaGetSymbolAddress((void**)&qc,  g_qc);
    cudaGetSymbolAddress((void**)&kc,  g_kc);
    cudaGetSymbolAddress((void**)&vc,  g_vc);
    cudaGetSymbolAddress((void**)&Wt,  g_Wt);

    tohalf3<<<dim3(M_TOTAL * D_MODEL / (256 * 4), 1, 3), 256>>>(q, k, v, qc, kc, vc);
    transpose_half4<<<dim3(32, 32, 4), 256>>>(Wq, Wk, Wv, Wo, Wt);

    cudaFuncSetAttribute(gemm_fp16<1>,
                         cudaFuncAttributeMaxDynamicSharedMemorySize, GEMM_SMEM_B);
    cudaFuncSetAttribute(gemm_fp16<0>,
                         cudaFuncAttributeMaxDynamicSharedMemorySize, GEMM_SMEM_B);
    cudaFuncSetAttribute(flash_fp16,
                         cudaFuncAttributeMaxDynamicSharedMemorySize, FLASH_SMEM_B);

    const size_t WSZ = (size_t)D_MODEL * D_MODEL;
    gemm_fp16<1><<<dim3(D_MODEL / 128, M_TOTAL / 128, 3), 256, GEMM_SMEM_B>>>(
        qc, kc, vc, Wt, Wt + WSZ, Wt + 2 * WSZ, bq, bk, bv, qh, kh, vh);

    flash_fp16<<<dim3(SEQ / 128, BATCH * HEADS), 256, FLASH_SMEM_B>>>(qh, kh, vh, att);

    gemm_fp16<0><<<dim3(D_MODEL / 128, M_TOTAL / 128, 1), 256, GEMM_SMEM_B>>>(
        att, att, att, Wt + 3 * WSZ, Wt + 3 * WSZ, Wt + 3 * WSZ,
        bo, bo, bo, out, out, out);
}

// round 10
// speedup vs baseline: 7.0493x; 1.0239x over previous
#include <cuda_runtime.h>
#include <cuda_fp16.h>
#include <math.h>
#include <stdint.h>

#define D_MODEL 1024
#define HEADS   16
#define DH      64
#define BATCH   4
#define SEQ     2048
#define M_TOTAL (BATCH * SEQ)   // 8192

// ---------------- scratch (device globals: allocation-guard safe) ----------------
__device__ __half g_qh[(size_t)BATCH * HEADS * SEQ * DH];   // [B,H,L,Dh] fp16 (q pre-scaled)
__device__ __half g_kh[(size_t)BATCH * HEADS * SEQ * DH];
__device__ __half g_vh[(size_t)BATCH * HEADS * SEQ * DH];
__device__ __half g_att[(size_t)M_TOTAL * D_MODEL];         // [B*L, D_MODEL] fp16
__device__ __half g_qc[(size_t)M_TOTAL * D_MODEL];          // fp16 inputs
__device__ __half g_kc[(size_t)M_TOTAL * D_MODEL];
__device__ __half g_vc[(size_t)M_TOTAL * D_MODEL];
__device__ __half g_Wt[(size_t)4 * D_MODEL * D_MODEL];      // fp16, transposed [n][k]

// ---------------- helpers ----------------
__device__ __forceinline__ uint32_t smem_u32(const void* p) {
    uint32_t a;
    asm("{ .reg .u64 t; cvta.to.shared.u64 t, %1; cvt.u32.u64 %0, t; }" : "=r"(a) : "l"(p));
    return a;
}

__device__ __forceinline__ uint32_t pack_h2(float lo, float hi) {
    uint32_t r;
    asm("cvt.rn.f16x2.f32 %0, %1, %2;" : "=r"(r) : "f"(hi), "f"(lo));
    return r;
}

__device__ __forceinline__ void mma_f16(float c[4], const uint32_t a[4], const uint32_t b[2]) {
    asm("mma.sync.aligned.m16n8k16.row.col.f32.f16.f16.f32 "
        "{%0,%1,%2,%3}, {%4,%5,%6,%7}, {%8,%9}, {%0,%1,%2,%3};"
        : "+f"(c[0]), "+f"(c[1]), "+f"(c[2]), "+f"(c[3])
        : "r"(a[0]), "r"(a[1]), "r"(a[2]), "r"(a[3]), "r"(b[0]), "r"(b[1]));
}

__device__ __forceinline__ void ldsm4(uint32_t r[4], uint32_t saddr) {
    asm volatile("ldmatrix.sync.aligned.m8n8.x4.shared.b16 {%0,%1,%2,%3}, [%4];"
        : "=r"(r[0]), "=r"(r[1]), "=r"(r[2]), "=r"(r[3]) : "r"(saddr));
}

__device__ __forceinline__ void ldsm4t(uint32_t r[4], uint32_t saddr) {
    asm volatile("ldmatrix.sync.aligned.m8n8.x4.trans.shared.b16 {%0,%1,%2,%3}, [%4];"
        : "=r"(r[0]), "=r"(r[1]), "=r"(r[2]), "=r"(r[3]) : "r"(saddr));
}

#define CPA16(dst, src) asm volatile("cp.async.cg.shared.global [%0], [%1], 16;" :: "r"(dst), "l"(src))
#define CPA_COMMIT()    asm volatile("cp.async.commit_group;")
#define CPA_WAIT0()     asm volatile("cp.async.wait_group 0;")

// ---------------- prologue converts ----------------
__global__ __launch_bounds__(256) void tohalf3(
    const float* __restrict__ a, const float* __restrict__ b, const float* __restrict__ c,
    __half* __restrict__ oa, __half* __restrict__ ob, __half* __restrict__ oc)
{
    const int z = blockIdx.z;
    const float* in = (z == 0) ? a : (z == 1) ? b : c;
    __half* out     = (z == 0) ? oa : (z == 1) ? ob : oc;
    const size_t i = ((size_t)blockIdx.x * 256 + threadIdx.x) * 4;
    float4 v = *(const float4*)(in + i);
    uint2 u = { pack_h2(v.x, v.y), pack_h2(v.z, v.w) };
    *(uint2*)(out + i) = u;
}

__global__ __launch_bounds__(256) void transpose_half4(
    const float* __restrict__ w0, const float* __restrict__ w1,
    const float* __restrict__ w2, const float* __restrict__ w3,
    __half* __restrict__ outbase)
{
    const int z = blockIdx.z;
    const float* in = (z == 0) ? w0 : (z == 1) ? w1 : (z == 2) ? w2 : w3;
    __half* out = outbase + (size_t)z * D_MODEL * D_MODEL;

    __shared__ float tile[32][33];
    const int tx = threadIdx.x & 31, ty = threadIdx.x >> 5;   // 32x8
    const int x = blockIdx.x * 32 + tx;
    const int y = blockIdx.y * 32 + ty;
#pragma unroll
    for (int j = 0; j < 32; j += 8)
        tile[ty + j][tx] = in[(size_t)(y + j) * D_MODEL + x];   // in[k][n]
    __syncthreads();
    const int x2 = blockIdx.y * 32 + tx;
    const int y2 = blockIdx.x * 32 + ty;
#pragma unroll
    for (int j = 0; j < 32; j += 8)
        out[(size_t)(y2 + j) * D_MODEL + x2] = __float2half_rn(tile[tx][ty + j]);  // out[n][k]
}

// ---------------- FP16 GEMM: CTA 128x256, warp 64x64, 2-stage cp.async ----------------
#define SSTR 72                         // fp16 per row (64 data + 8 pad) = 144B
#define A_ROWS 128
#define B_ROWS 256
#define ST_A_HALF (A_ROWS * SSTR)
#define STAGE_B ((A_ROWS + B_ROWS) * SSTR * 2)   // 55296
#define GEMM_SMEM_B (2 * STAGE_B)                // 110592

template <int HEADSPLIT>
__global__ __launch_bounds__(256) void gemm_fp16(
    const __half* __restrict__ A0, const __half* __restrict__ A1, const __half* __restrict__ A2,
    const __half* __restrict__ T0, const __half* __restrict__ T1, const __half* __restrict__ T2,
    const float* __restrict__ b0, const float* __restrict__ b1, const float* __restrict__ b2,
    void* __restrict__ C0, void* __restrict__ C1, void* __restrict__ C2)
{
    const int z = blockIdx.z;
    const __half* A   = (z == 0) ? A0 : (z == 1) ? A1 : A2;
    const __half* Wt  = (z == 0) ? T0 : (z == 1) ? T1 : T2;
    const float* bias = (z == 0) ? b0 : (z == 1) ? b1 : b2;
    void* C           = (z == 0) ? C0 : (z == 1) ? C1 : C2;
    const float oscale = (HEADSPLIT && z == 0) ? 0.125f : 1.0f;   // fold 1/sqrt(Dh) into q

    extern __shared__ __half sh[];
    const uint32_t sbase = smem_u32(sh);
    const int tid = threadIdx.x;
    const int lane = tid & 31;
    const int w = tid >> 5;
    const int g = lane >> 2, t = lane & 3;
    const int wm = w >> 2, wn = w & 3;           // 2 x 4 warps -> 64x64 tiles
    const int bm = blockIdx.y * 128, bn = blockIdx.x * 256;

    float acc[4][8][4];
#pragma unroll
    for (int mt = 0; mt < 4; mt++)
#pragma unroll
        for (int nt = 0; nt < 8; nt++)
#pragma unroll
            for (int i = 0; i < 4; i++) acc[mt][nt][i] = 0.f;

    // cp.async: A row tid>>1 (half tid&1); B rows tid>>1 and +128 (half tid&1)
    const int srow = tid >> 1;
    const int soff = (tid & 1) << 5;
    const __half* Ag  = A  + (size_t)(bm + srow) * D_MODEL + soff;
    const __half* Bg0 = Wt + (size_t)(bn + srow) * D_MODEL + soff;
    const __half* Bg1 = Bg0 + (size_t)128 * D_MODEL;
    const uint32_t ad0  = sbase + (uint32_t)(srow * SSTR + soff) * 2u;
    const uint32_t bd0  = ad0 + (uint32_t)ST_A_HALF * 2u;
    const uint32_t bd1  = bd0 + (uint32_t)(128 * SSTR) * 2u;

    // prologue: tile 0 -> stage 0
#pragma unroll
    for (int j = 0; j < 4; j++) CPA16(ad0 + j * 16, Ag + j * 8);
#pragma unroll
    for (int j = 0; j < 4; j++) CPA16(bd0 + j * 16, Bg0 + j * 8);
#pragma unroll
    for (int j = 0; j < 4; j++) CPA16(bd1 + j * 16, Bg1 + j * 8);
    CPA_COMMIT();

    // fragment bases
    const int lrow = (lane & 7) + ((lane >> 3) & 1) * 8;
    const uint32_t a_frag0 = sbase + (uint32_t)(((wm * 64) + lrow) * SSTR + (lane >> 4) * 8) * 2u;
    const int bn_lane = (lane & 7) + (lane >> 4) * 8;
    const int k_lane = ((lane >> 3) & 1) * 8;
    const uint32_t b_frag0 = sbase + (uint32_t)ST_A_HALF * 2u
                           + (uint32_t)((wn * 64 + bn_lane) * SSTR + k_lane) * 2u;

    for (int i = 0; i < 16; i++) {
        CPA_WAIT0();
        __syncthreads();
        if (i + 1 < 16) {
            const int nb = (i + 1) & 1;
            const int k0 = (i + 1) * 64;
            const uint32_t so = (uint32_t)(nb * STAGE_B);
#pragma unroll
            for (int j = 0; j < 4; j++) CPA16(ad0 + so + j * 16, Ag + k0 + j * 8);
#pragma unroll
            for (int j = 0; j < 4; j++) CPA16(bd0 + so + j * 16, Bg0 + k0 + j * 8);
#pragma unroll
            for (int j = 0; j < 4; j++) CPA16(bd1 + so + j * 16, Bg1 + k0 + j * 8);
            CPA_COMMIT();
        }
        const uint32_t so = (uint32_t)((i & 1) * STAGE_B);
        const uint32_t ab = a_frag0 + so;
        const uint32_t bb = b_frag0 + so;
#pragma unroll
        for (int ks = 0; ks < 4; ks++) {
            uint32_t a[4][4], b[8][2];
#pragma unroll
            for (int mt = 0; mt < 4; mt++)
                ldsm4(a[mt], ab + (uint32_t)(mt * 16 * SSTR) * 2u + ks * 32);
#pragma unroll
            for (int p = 0; p < 4; p++) {
                uint32_t r4[4];
                ldsm4(r4, bb + (uint32_t)(p * 16 * SSTR) * 2u + ks * 32);
                b[2 * p][0] = r4[0];     b[2 * p][1] = r4[1];
                b[2 * p + 1][0] = r4[2]; b[2 * p + 1][1] = r4[3];
            }
#pragma unroll
            for (int mt = 0; mt < 4; mt++)
#pragma unroll
                for (int nt = 0; nt < 8; nt++)
                    mma_f16(acc[mt][nt], a[mt], b[nt]);
        }
    }

    // epilogue
#pragma unroll
    for (int mt = 0; mt < 4; mt++) {
#pragma unroll
        for (int nt = 0; nt < 8; nt++) {
            const int r0 = bm + wm * 64 + mt * 16 + g;
            const int c0 = bn + wn * 64 + nt * 8 + 2 * t;
#pragma unroll
            for (int i = 0; i < 4; i++) {
                const int row = r0 + (i >> 1) * 8;
                const int col = c0 + (i & 1);
                const float v = (acc[mt][nt][i] + bias[col]) * oscale;
                if (HEADSPLIT) {
                    const int b = row >> 11, l = row & (SEQ - 1);
                    const int h = col >> 6,  d = col & 63;
                    ((__half*)C)[(((size_t)(b * HEADS + h) * SEQ + l) << 6) + d] =
                        __float2half_rn(v);
                } else {
                    ((float*)C)[(size_t)row * D_MODEL + col] = v;
                }
            }
        }
    }
}

// ---------------- FP16 flash attention: cp.async, ldsm Q/K, ldsm.trans V ----------------
// BQ=128, BK=64, 256 threads, warp = 16 q-rows. Q arrives pre-scaled by 0.125.
#define FSTR 72
#define QB_BYTES (128 * FSTR * 2)    // 18432
#define KB_BYTES (64 * FSTR * 2)     // 9216
#define FLASH_SMEM_B (QB_BYTES + 4 * KB_BYTES)  // 55296

__global__ __launch_bounds__(256) void flash_fp16(
    const __half* __restrict__ Q, const __half* __restrict__ K,
    const __half* __restrict__ V, __half* __restrict__ O)
{
    extern __shared__ __half sm[];
    const uint32_t sbase = smem_u32(sm);
    const uint32_t kbase = sbase + QB_BYTES;
    const uint32_t vbase = kbase + 2 * KB_BYTES;

    const int tid = threadIdx.x;
    const int lane = tid & 31;
    const int w = tid >> 5;
    const int g = lane >> 2, t = lane & 3;
    const int bh = blockIdx.y;
    const int bx = blockIdx.x;
    const int q0 = bx * 128;

    const __half* Qb = Q + (size_t)bh * SEQ * DH;
    const __half* Kb = K + (size_t)bh * SEQ * DH;
    const __half* Vb = V + (size_t)bh * SEQ * DH;

    const int qrow = tid >> 1, qoff = (tid & 1) * 32;
    const int krow = tid >> 2, koff = (tid & 3) * 16;
    const uint32_t qdst0 = sbase + (uint32_t)(qrow * FSTR + qoff) * 2u;
    const uint32_t kdst0 = kbase + (uint32_t)(krow * FSTR + koff) * 2u;
    const uint32_t vdst0 = vbase + (uint32_t)(krow * FSTR + koff) * 2u;
    const __half* Qg = Qb + (size_t)(q0 + qrow) * DH + qoff;
    const __half* Kg = Kb + (size_t)krow * DH + koff;
    const __half* Vg = Vb + (size_t)krow * DH + koff;

#pragma unroll
    for (int j = 0; j < 4; j++) CPA16(qdst0 + j * 16, Qg + j * 8);
#pragma unroll
    for (int j = 0; j < 2; j++) CPA16(kdst0 + j * 16, Kg + j * 8);
#pragma unroll
    for (int j = 0; j < 2; j++) CPA16(vdst0 + j * 16, Vg + j * 8);
    CPA_COMMIT();

    const int lrow = (lane & 7) + ((lane >> 3) & 1) * 8;
    const uint32_t q_frag0 = sbase + (uint32_t)((w * 16 + lrow) * FSTR + (lane >> 4) * 8) * 2u;
    const int bn_lane = (lane & 7) + (lane >> 4) * 8;
    const int k_lane = ((lane >> 3) & 1) * 8;
    const uint32_t k_frag0 = kbase + (uint32_t)(bn_lane * FSTR + k_lane) * 2u;
    const uint32_t v_frag0 = vbase + (uint32_t)(lrow * FSTR + (lane >> 4) * 8) * 2u;

    float oacc[8][4];
#pragma unroll
    for (int dt = 0; dt < 8; dt++)
#pragma unroll
        for (int i = 0; i < 4; i++) oacc[dt][i] = 0.f;
    float m0 = -INFINITY, m1 = -INFINITY, l0 = 0.f, l1 = 0.f;

    const int qr = q0 + w * 16 + g;
    const int jmax = 2 * bx + 1;

    for (int j = 0; j <= jmax; j++) {
        CPA_WAIT0();
        __syncthreads();
        if (j + 1 <= jmax) {
            const int nb = (j + 1) & 1;
            const size_t koffg = (size_t)(j + 1) * 64 * DH;
#pragma unroll
            for (int jj = 0; jj < 2; jj++)
                CPA16(kdst0 + (uint32_t)(nb * KB_BYTES) + jj * 16, Kg + koffg + jj * 8);
#pragma unroll
            for (int jj = 0; jj < 2; jj++)
                CPA16(vdst0 + (uint32_t)(nb * KB_BYTES) + jj * 16, Vg + koffg + jj * 8);
            CPA_COMMIT();
        }
        const int buf = j & 1;
        const uint32_t kf = k_frag0 + (uint32_t)(buf * KB_BYTES);
        const uint32_t vf = v_frag0 + (uint32_t)(buf * KB_BYTES);
        const int k0 = j * 64;

        // S = Q K^T (Q pre-scaled)
        float sacc[8][4];
#pragma unroll
        for (int nt = 0; nt < 8; nt++)
#pragma unroll
            for (int i = 0; i < 4; i++) sacc[nt][i] = 0.f;
#pragma unroll
        for (int kt = 0; kt < 4; kt++) {
            uint32_t qf[4];
            ldsm4(qf, q_frag0 + kt * 32);
            uint32_t kb[8][2];
#pragma unroll
            for (int p = 0; p < 4; p++) {
                uint32_t r4[4];
                ldsm4(r4, kf + (uint32_t)(p * 16 * FSTR) * 2u + kt * 32);
                kb[2 * p][0] = r4[0];     kb[2 * p][1] = r4[1];
                kb[2 * p + 1][0] = r4[2]; kb[2 * p + 1][1] = r4[3];
            }
#pragma unroll
            for (int nt = 0; nt < 8; nt++)
                mma_f16(sacc[nt], qf, kb[nt]);
        }

        // causal mask: only on the two diagonal-adjacent tiles
        if (j >= 2 * bx) {
#pragma unroll
            for (int nt = 0; nt < 8; nt++) {
                const int c0 = k0 + nt * 8 + 2 * t;
#pragma unroll
                for (int i = 0; i < 4; i++) {
                    const int row = (i >> 1) ? qr + 8 : qr;
                    const int col = c0 + (i & 1);
                    if (col > row) sacc[nt][i] = -INFINITY;
                }
            }
        }

        // online softmax
        float mt0 = -INFINITY, mt1 = -INFINITY;
#pragma unroll
        for (int nt = 0; nt < 8; nt++) {
            mt0 = fmaxf(mt0, fmaxf(sacc[nt][0], sacc[nt][1]));
            mt1 = fmaxf(mt1, fmaxf(sacc[nt][2], sacc[nt][3]));
        }
        mt0 = fmaxf(mt0, __shfl_xor_sync(0xffffffffu, mt0, 1));
        mt0 = fmaxf(mt0, __shfl_xor_sync(0xffffffffu, mt0, 2));
        mt1 = fmaxf(mt1, __shfl_xor_sync(0xffffffffu, mt1, 1));
        mt1 = fmaxf(mt1, __shfl_xor_sync(0xffffffffu, mt1, 2));

        const float mn0 = fmaxf(m0, mt0), mn1 = fmaxf(m1, mt1);
        const float cor0 = __expf(m0 - mn0), cor1 = __expf(m1 - mn1);
        m0 = mn0; m1 = mn1;

        float rs0 = 0.f, rs1 = 0.f;
#pragma unroll
        for (int nt = 0; nt < 8; nt++) {
            const float p00 = __expf(sacc[nt][0] - m0);
            const float p01 = __expf(sacc[nt][1] - m0);
            const float p10 = __expf(sacc[nt][2] - m1);
            const float p11 = __expf(sacc[nt][3] - m1);
            rs0 += p00 + p01; rs1 += p10 + p11;
            sacc[nt][0] = p00; sacc[nt][1] = p01;
            sacc[nt][2] = p10; sacc[nt][3] = p11;
        }
        rs0 += __shfl_xor_sync(0xffffffffu, rs0, 1);
        rs0 += __shfl_xor_sync(0xffffffffu, rs0, 2);
        rs1 += __shfl_xor_sync(0xffffffffu, rs1, 1);
        rs1 += __shfl_xor_sync(0xffffffffu, rs1, 2);
        l0 = l0 * cor0 + rs0;
        l1 = l1 * cor1 + rs1;
#pragma unroll
        for (int dt = 0; dt < 8; dt++) {
            oacc[dt][0] *= cor0; oacc[dt][1] *= cor0;
            oacc[dt][2] *= cor1; oacc[dt][3] *= cor1;
        }

        // O += P @ V
#pragma unroll
        for (int kt2 = 0; kt2 < 4; kt2++) {
            uint32_t pa[4];
            pa[0] = pack_h2(sacc[2 * kt2][0],     sacc[2 * kt2][1]);
            pa[1] = pack_h2(sacc[2 * kt2][2],     sacc[2 * kt2][3]);
            pa[2] = pack_h2(sacc[2 * kt2 + 1][0], sacc[2 * kt2 + 1][1]);
            pa[3] = pack_h2(sacc[2 * kt2 + 1][2], sacc[2 * kt2 + 1][3]);
#pragma unroll
            for (int pd = 0; pd < 4; pd++) {
                uint32_t r4[4];
                ldsm4t(r4, vf + (uint32_t)(kt2 * 16 * FSTR + pd * 16) * 2u);
                uint32_t vb0[2] = { r4[0], r4[1] };
                uint32_t vb1[2] = { r4[2], r4[3] };
                mma_f16(oacc[2 * pd],     pa, vb0);
                mma_f16(oacc[2 * pd + 1], pa, vb1);
            }
        }
    }

    // write back into [B, L, D_MODEL] as fp16
    const int b = bh >> 4, h = bh & 15;
    const float inv0 = 1.f / l0, inv1 = 1.f / l1;
#pragma unroll
    for (int dt = 0; dt < 8; dt++) {
        const int col = h * DH + dt * 8 + 2 * t;
        __half* o0 = &O[(size_t)(b * SEQ + qr)     * D_MODEL + col];
        __half* o1 = &O[(size_t)(b * SEQ + qr + 8) * D_MODEL + col];
        *(uint32_t*)o0 = pack_h2(oacc[dt][0] * inv0, oacc[dt][1] * inv0);
        *(uint32_t*)o1 = pack_h2(oacc[dt][2] * inv1, oacc[dt][3] * inv1);
    }
}

// ---------------- launch ----------------
extern "C" void kernel_launch(void* const* d_in, const int* in_sizes, int n_in,
                              void* d_out, int out_size)
{
    const float* q  = (const float*)d_in[0];
    const float* k  = (const float*)d_in[1];
    const float* v  = (const float*)d_in[2];
    const float* Wq = (const float*)d_in[3];
    const float* bq = (const float*)d_in[4];
    const float* Wk = (const float*)d_in[5];
    const float* bk = (const float*)d_in[6];
    const float* Wv = (const float*)d_in[7];
    const float* bv = (const float*)d_in[8];
    const float* Wo = (const float*)d_in[9];
    const float* bo = (const float*)d_in[10];
    float* out = (float*)d_out;

    __half *qh, *kh, *vh, *att, *qc, *kc, *vc, *Wt;
    cudaGetSymbolAddress((void**)&qh,  g_qh);
    cudaGetSymbolAddress((void**)&kh,  g_kh);
    cudaGetSymbolAddress((void**)&vh,  g_vh);
    cudaGetSymbolAddress((void**)&att, g_att);
    cudaGetSymbolAddress((void**)&qc,  g_qc);
    cudaGetSymbolAddress((void**)&kc,  g_kc);
    cudaGetSymbolAddress((void**)&vc,  g_vc);
    cudaGetSymbolAddress((void**)&Wt,  g_Wt);

    tohalf3<<<dim3(M_TOTAL * D_MODEL / (256 * 4), 1, 3), 256>>>(q, k, v, qc, kc, vc);
    transpose_half4<<<dim3(32, 32, 4), 256>>>(Wq, Wk, Wv, Wo, Wt);

    cudaFuncSetAttribute(gemm_fp16<1>,
                         cudaFuncAttributeMaxDynamicSharedMemorySize, GEMM_SMEM_B);
    cudaFuncSetAttribute(gemm_fp16<0>,
                         cudaFuncAttributeMaxDynamicSharedMemorySize, GEMM_SMEM_B);
    cudaFuncSetAttribute(flash_fp16,
                         cudaFuncAttributeMaxDynamicSharedMemorySize, FLASH_SMEM_B);

    const size_t WSZ = (size_t)D_MODEL * D_MODEL;
    gemm_fp16<1><<<dim3(D_MODEL / 256, M_TOTAL / 128, 3), 256, GEMM_SMEM_B>>>(
        qc, kc, vc, Wt, Wt + WSZ, Wt + 2 * WSZ, bq, bk, bv, qh, kh, vh);

    flash_fp16<<<dim3(SEQ / 128, BATCH * HEADS), 256, FLASH_SMEM_B>>>(qh, kh, vh, att);

    gemm_fp16<0><<<dim3(D_MODEL / 256, M_TOTAL / 128, 1), 256, GEMM_SMEM_B>>>(
        att, att, att, Wt + 3 * WSZ, Wt + 3 * WSZ, Wt + 3 * WSZ,
        bo, bo, bo, out, out, out);
}